// round 1
// baseline (speedup 1.0000x reference)
#include <cuda_runtime.h>

// Problem constants
constexpr int B = 16;
constexpr int T = 2048;
constexpr int D = 256;
constexpr int MBIG = B * T;          // 32768
__device__ __constant__ float GAMMA_C = 0.9f;

// Scratch (static device globals — no runtime allocation)
__device__ float g_wvsum[D];
__device__ float g_y[T * D];
__device__ float g_c[T * D];
__device__ float g_S[T * D];

// ---------------------------------------------------------------------------
// Kernel A: wv_sum[i] = sum_j Wv[i][j]
// ---------------------------------------------------------------------------
__global__ void wvsum_kernel(const float* __restrict__ Wv) {
    int i = threadIdx.x;
    float s = 0.f;
#pragma unroll 8
    for (int j = 0; j < D; ++j) s += Wv[i * D + j];
    g_wvsum[i] = s;
}

// ---------------------------------------------------------------------------
// Kernel B: per-t fold over batch.
//   vsum[b] = x[b,t,:] . wv_sum
//   y[t,d]  = sum_b vsum[b] * x[b,t,d]
// One block per t (2048 blocks, 256 threads). Reads x exactly once (32 MB).
// ---------------------------------------------------------------------------
__global__ void y_kernel(const float* __restrict__ x) {
    const int t = blockIdx.x;
    const int d = threadIdx.x;
    __shared__ float xs[B][D];
    __shared__ float wvs[D];
    __shared__ float vs[B];

    wvs[d] = g_wvsum[d];
#pragma unroll
    for (int b = 0; b < B; ++b)
        xs[b][d] = x[((size_t)b * T + t) * D + d];
    __syncthreads();

    const int warp = d >> 5, lane = d & 31;
#pragma unroll
    for (int bb = 0; bb < 2; ++bb) {
        const int b = warp * 2 + bb;
        float p = 0.f;
#pragma unroll
        for (int i = 0; i < D / 32; ++i)
            p += xs[b][lane + 32 * i] * wvs[lane + 32 * i];
#pragma unroll
        for (int o = 16; o > 0; o >>= 1)
            p += __shfl_xor_sync(0xffffffffu, p, o);
        if (lane == 0) vs[b] = p;
    }
    __syncthreads();

    float acc = 0.f;
#pragma unroll
    for (int b = 0; b < B; ++b)
        acc += vs[b] * xs[b][d];
    g_y[t * D + d] = acc;
}

// ---------------------------------------------------------------------------
// Kernel D: sequential decay scan over t.
//   r[t][d] = gamma*r[t-1][d] + c[t][d],  t = 1..T-1
//   S[t]    = r[t] (t>=1), S[0] = r[1]
// Single block of 256 threads (one per d). Serial FMA chain, ~5-8 us.
// ---------------------------------------------------------------------------
__global__ void scan_kernel() {
    const int d = threadIdx.x;
    const float g = GAMMA_C;
    float r = 0.f;
#pragma unroll 8
    for (int t = 1; t < T; ++t) {
        r = g * r + g_c[t * D + d];
        g_S[t * D + d] = r;
    }
    // S[0][d] = rows[0][d] = c[1][d]
    g_S[d] = g_c[D + d];
}

// ---------------------------------------------------------------------------
// SGEMM: C[m,n] = (scale?) * sum_k A[m,k]*Bm[k,n], N=K=256 fixed.
// BM=BN=128, BK=16, 256 threads, 8x8 per-thread microtile.
// SCALED epilogue applies the reshape-scramble: scale = g_S[n*T + (m % T)].
// ---------------------------------------------------------------------------
template <bool SCALED>
__global__ __launch_bounds__(256)
void sgemm_kernel(const float* __restrict__ A, const float* __restrict__ Bm,
                  float* __restrict__ C) {
    constexpr int N = 256, K = 256;
    constexpr int BM = 128, BN = 128, BK = 16;
    __shared__ float As[BK][BM];   // A stored transposed
    __shared__ float Bs[BK][BN];

    const int bm = blockIdx.x * BM;
    const int bn = blockIdx.y * BN;
    const int tid = threadIdx.x;
    const int tx = tid & 15;   // column group (8 cols)
    const int ty = tid >> 4;   // row group (8 rows)

    float acc[8][8];
#pragma unroll
    for (int i = 0; i < 8; ++i)
#pragma unroll
        for (int j = 0; j < 8; ++j) acc[i][j] = 0.f;

    for (int k0 = 0; k0 < K; k0 += BK) {
#pragma unroll
        for (int i2 = 0; i2 < 2; ++i2) {
            const int idx = tid + i2 * 256;
            // A tile: 128 rows x 16 cols -> transposed store
            const int ar = idx >> 2, ac4 = idx & 3;
            float4 v = *reinterpret_cast<const float4*>(
                &A[(size_t)(bm + ar) * K + k0 + ac4 * 4]);
            As[ac4 * 4 + 0][ar] = v.x;
            As[ac4 * 4 + 1][ar] = v.y;
            As[ac4 * 4 + 2][ar] = v.z;
            As[ac4 * 4 + 3][ar] = v.w;
            // B tile: 16 rows x 128 cols
            const int br = idx >> 5, bc4 = idx & 31;
            float4 w = *reinterpret_cast<const float4*>(
                &Bm[(size_t)(k0 + br) * N + bn + bc4 * 4]);
            *reinterpret_cast<float4*>(&Bs[br][bc4 * 4]) = w;
        }
        __syncthreads();

#pragma unroll
        for (int k = 0; k < BK; ++k) {
            float af[8], bf[8];
            *reinterpret_cast<float4*>(af)     = *reinterpret_cast<const float4*>(&As[k][ty * 8]);
            *reinterpret_cast<float4*>(af + 4) = *reinterpret_cast<const float4*>(&As[k][ty * 8 + 4]);
            *reinterpret_cast<float4*>(bf)     = *reinterpret_cast<const float4*>(&Bs[k][tx * 8]);
            *reinterpret_cast<float4*>(bf + 4) = *reinterpret_cast<const float4*>(&Bs[k][tx * 8 + 4]);
#pragma unroll
            for (int i = 0; i < 8; ++i)
#pragma unroll
                for (int j = 0; j < 8; ++j)
                    acc[i][j] += af[i] * bf[j];
        }
        __syncthreads();
    }

#pragma unroll
    for (int i = 0; i < 8; ++i) {
        const int row = bm + ty * 8 + i;
        const int t = row & (T - 1);
#pragma unroll
        for (int j4 = 0; j4 < 2; ++j4) {
            const int col = bn + tx * 8 + j4 * 4;
            float4 o;
            float* po = &o.x;
#pragma unroll
            for (int j = 0; j < 4; ++j) {
                float v = acc[i][j4 * 4 + j];
                if (SCALED) v *= g_S[(size_t)(col + j) * T + t];
                po[j] = v;
            }
            *reinterpret_cast<float4*>(&C[(size_t)row * N + col]) = o;
        }
    }
}

// ---------------------------------------------------------------------------
extern "C" void kernel_launch(void* const* d_in, const int* in_sizes, int n_in,
                              void* d_out, int out_size) {
    const float* x  = (const float*)d_in[0];
    const float* Wq = (const float*)d_in[1];
    const float* Wk = (const float*)d_in[2];
    const float* Wv = (const float*)d_in[3];
    float* out = (float*)d_out;

    void* py = nullptr;
    void* pc = nullptr;
    cudaGetSymbolAddress(&py, g_y);
    cudaGetSymbolAddress(&pc, g_c);

    // A: row-sums of Wv
    wvsum_kernel<<<1, 256>>>(Wv);
    // B: vsum fold + y
    y_kernel<<<T, 256>>>(x);
    // C: c = y @ Wk   (M=2048 -> grid 16x2)
    sgemm_kernel<false><<<dim3(T / 128, 2), 256>>>((const float*)py, Wk, (float*)pc);
    // D: decay scan -> S
    scan_kernel<<<1, 256>>>();
    // E: out = S2 .* (x @ Wq)   (M=32768 -> grid 256x2)
    sgemm_kernel<true><<<dim3(MBIG / 128, 2), 256>>>(x, Wq, out);
}

// round 5
// speedup vs baseline: 3.4116x; 3.4116x over previous
#include <cuda_runtime.h>

// Problem constants
constexpr int B = 16;
constexpr int T = 2048;
constexpr int D = 256;
constexpr int MBIG = B * T;          // 32768
constexpr int SCAN_L = 32;           // chunk length
constexpr int SCAN_P = T / SCAN_L;   // 64 chunks
constexpr float GAMMA   = 0.9f;
constexpr float GAMMA32 = 0.03433683820292512f;  // 0.9^32

// Scratch (static device globals — no runtime allocation)
__device__ float g_wvsum[D];
__device__ float g_y[T * D];
__device__ float g_c[T * D];
__device__ float g_S[T * D];
__device__ float g_carry[SCAN_P * D];
__device__ float g_pre[SCAN_P * D];

// ---------------------------------------------------------------------------
// Kernel A: wv_sum[i] = sum_j Wv[i][j]
// ---------------------------------------------------------------------------
__global__ void wvsum_kernel(const float* __restrict__ Wv) {
    int i = threadIdx.x;
    float s = 0.f;
#pragma unroll 8
    for (int j = 0; j < D; ++j) s += Wv[i * D + j];
    g_wvsum[i] = s;
}

// ---------------------------------------------------------------------------
// Kernel B: per-t fold over batch.
//   vsum[b] = x[b,t,:] . wv_sum
//   y[t,d]  = sum_b vsum[b] * x[b,t,d]
// ---------------------------------------------------------------------------
__global__ void y_kernel(const float* __restrict__ x) {
    const int t = blockIdx.x;
    const int d = threadIdx.x;
    __shared__ float xs[B][D];
    __shared__ float wvs[D];
    __shared__ float vs[B];

    wvs[d] = g_wvsum[d];
#pragma unroll
    for (int b = 0; b < B; ++b)
        xs[b][d] = x[((size_t)b * T + t) * D + d];
    __syncthreads();

    const int warp = d >> 5, lane = d & 31;
#pragma unroll
    for (int bb = 0; bb < 2; ++bb) {
        const int b = warp * 2 + bb;
        float p = 0.f;
#pragma unroll
        for (int i = 0; i < D / 32; ++i)
            p += xs[b][lane + 32 * i] * wvs[lane + 32 * i];
#pragma unroll
        for (int o = 16; o > 0; o >>= 1)
            p += __shfl_xor_sync(0xffffffffu, p, o);
        if (lane == 0) vs[b] = p;
    }
    __syncthreads();

    float acc = 0.f;
#pragma unroll
    for (int b = 0; b < B; ++b)
        acc += vs[b] * xs[b][d];
    g_y[t * D + d] = acc;
}

// ---------------------------------------------------------------------------
// Blocked decay scan: r[t] = gamma*r[t-1] + chat[t], chat[0]=0, chat[t]=c[t].
// S[t] = r[t] (t>=1), S[0] = r[1].
//
// D1: per-chunk local scan (loads batched up-front for MLP)
// ---------------------------------------------------------------------------
__global__ __launch_bounds__(256) void scan_local_kernel() {
    const int p = blockIdx.x, d = threadIdx.x;
    float v[SCAN_L];
#pragma unroll
    for (int i = 0; i < SCAN_L; ++i) {
        const int t = p * SCAN_L + i;
        v[i] = (t == 0) ? 0.f : g_c[t * D + d];
    }
    float r = 0.f;
#pragma unroll
    for (int i = 0; i < SCAN_L; ++i) {
        r = GAMMA * r + v[i];
        v[i] = r;
    }
#pragma unroll
    for (int i = 0; i < SCAN_L; ++i)
        g_S[(p * SCAN_L + i) * D + d] = v[i];
    g_carry[p * D + d] = r;
}

// D2: scan carries across chunks; g_pre[p] = global r at end of chunk p-1.
__global__ __launch_bounds__(256) void scan_carry_kernel() {
    const int d = threadIdx.x;
    float c[SCAN_P];
#pragma unroll
    for (int p = 0; p < SCAN_P; ++p)
        c[p] = g_carry[p * D + d];
    float r = 0.f;
#pragma unroll
    for (int p = 0; p < SCAN_P; ++p) {
        g_pre[p * D + d] = r;
        r = c[p] + GAMMA32 * r;
    }
}

// D3: combine local + gamma^{i+1} * prefix; patch S[0] = r[1].
__global__ __launch_bounds__(256) void scan_combine_kernel() {
    const int p = blockIdx.x, d = threadIdx.x;
    const float pre = g_pre[p * D + d];
    float v[SCAN_L];
#pragma unroll
    for (int i = 0; i < SCAN_L; ++i)
        v[i] = g_S[(p * SCAN_L + i) * D + d];
    float gp = GAMMA;
#pragma unroll
    for (int i = 0; i < SCAN_L; ++i) {
        v[i] += gp * pre;
        gp *= GAMMA;
    }
#pragma unroll
    for (int i = 0; i < SCAN_L; ++i)
        g_S[(p * SCAN_L + i) * D + d] = v[i];
    if (p == 0)
        g_S[d] = v[1];   // S[0] := r[1]
}

// ---------------------------------------------------------------------------
// SGEMM: C[m,n] = (scale?) * sum_k A[m,k]*Bm[k,n], N=K=256 fixed.
// BM=BN=128, BK=16, 256 threads, 8x8 per-thread microtile.
// SCALED epilogue applies the reshape-scramble: scale = g_S[n*T + (m % T)].
// ---------------------------------------------------------------------------
template <bool SCALED>
__global__ __launch_bounds__(256)
void sgemm_kernel(const float* __restrict__ A, const float* __restrict__ Bm,
                  float* __restrict__ C) {
    constexpr int N = 256, K = 256;
    constexpr int BM = 128, BN = 128, BK = 16;
    __shared__ float As[BK][BM];   // A stored transposed
    __shared__ float Bs[BK][BN];

    const int bm = blockIdx.x * BM;
    const int bn = blockIdx.y * BN;
    const int tid = threadIdx.x;
    const int tx = tid & 15;   // column group (8 cols)
    const int ty = tid >> 4;   // row group (8 rows)

    float acc[8][8];
#pragma unroll
    for (int i = 0; i < 8; ++i)
#pragma unroll
        for (int j = 0; j < 8; ++j) acc[i][j] = 0.f;

    for (int k0 = 0; k0 < K; k0 += BK) {
#pragma unroll
        for (int i2 = 0; i2 < 2; ++i2) {
            const int idx = tid + i2 * 256;
            // A tile: 128 rows x 16 cols -> transposed store
            const int ar = idx >> 2, ac4 = idx & 3;
            float4 v = *reinterpret_cast<const float4*>(
                &A[(size_t)(bm + ar) * K + k0 + ac4 * 4]);
            As[ac4 * 4 + 0][ar] = v.x;
            As[ac4 * 4 + 1][ar] = v.y;
            As[ac4 * 4 + 2][ar] = v.z;
            As[ac4 * 4 + 3][ar] = v.w;
            // B tile: 16 rows x 128 cols
            const int br = idx >> 5, bc4 = idx & 31;
            float4 w = *reinterpret_cast<const float4*>(
                &Bm[(size_t)(k0 + br) * N + bn + bc4 * 4]);
            *reinterpret_cast<float4*>(&Bs[br][bc4 * 4]) = w;
        }
        __syncthreads();

#pragma unroll
        for (int k = 0; k < BK; ++k) {
            float af[8], bf[8];
            *reinterpret_cast<float4*>(af)     = *reinterpret_cast<const float4*>(&As[k][ty * 8]);
            *reinterpret_cast<float4*>(af + 4) = *reinterpret_cast<const float4*>(&As[k][ty * 8 + 4]);
            *reinterpret_cast<float4*>(bf)     = *reinterpret_cast<const float4*>(&Bs[k][tx * 8]);
            *reinterpret_cast<float4*>(bf + 4) = *reinterpret_cast<const float4*>(&Bs[k][tx * 8 + 4]);
#pragma unroll
            for (int i = 0; i < 8; ++i)
#pragma unroll
                for (int j = 0; j < 8; ++j)
                    acc[i][j] += af[i] * bf[j];
        }
        __syncthreads();
    }

#pragma unroll
    for (int i = 0; i < 8; ++i) {
        const int row = bm + ty * 8 + i;
        const int t = row & (T - 1);
#pragma unroll
        for (int j4 = 0; j4 < 2; ++j4) {
            const int col = bn + tx * 8 + j4 * 4;
            float4 o;
            float* po = &o.x;
#pragma unroll
            for (int j = 0; j < 4; ++j) {
                float v = acc[i][j4 * 4 + j];
                if (SCALED) v *= g_S[(size_t)(col + j) * T + t];
                po[j] = v;
            }
            *reinterpret_cast<float4*>(&C[(size_t)row * N + col]) = o;
        }
    }
}

// ---------------------------------------------------------------------------
extern "C" void kernel_launch(void* const* d_in, const int* in_sizes, int n_in,
                              void* d_out, int out_size) {
    const float* x  = (const float*)d_in[0];
    const float* Wq = (const float*)d_in[1];
    const float* Wk = (const float*)d_in[2];
    const float* Wv = (const float*)d_in[3];
    float* out = (float*)d_out;

    void* py = nullptr;
    void* pc = nullptr;
    cudaGetSymbolAddress(&py, g_y);
    cudaGetSymbolAddress(&pc, g_c);

    // A: row-sums of Wv
    wvsum_kernel<<<1, 256>>>(Wv);
    // B: vsum fold + y
    y_kernel<<<T, 256>>>(x);
    // C: c = y @ Wk   (M=2048 -> grid 16x2)
    sgemm_kernel<false><<<dim3(T / 128, 2), 256>>>((const float*)py, Wk, (float*)pc);
    // D: blocked decay scan -> S
    scan_local_kernel<<<SCAN_P, 256>>>();
    scan_carry_kernel<<<1, 256>>>();
    scan_combine_kernel<<<SCAN_P, 256>>>();
    // E: out = S2 .* (x @ Wq)   (M=32768 -> grid 256x2)
    sgemm_kernel<true><<<dim3(MBIG / 128, 2), 256>>>(x, Wq, out);
}

// round 10
// speedup vs baseline: 5.6402x; 1.6532x over previous
#include <cuda_runtime.h>
#include <cuda_bf16.h>
#include <cstdint>

// Problem constants
constexpr int B = 16;
constexpr int T = 2048;
constexpr int D = 256;
constexpr int MBIG = B * T;          // 32768
constexpr int SCAN_L = 32;
constexpr int SCAN_P = T / SCAN_L;   // 64
constexpr float GAMMA   = 0.9f;
constexpr float GAMMA32 = 0.03433683820292512f;  // 0.9^32

// ---------------------------------------------------------------------------
// Static device scratch
// ---------------------------------------------------------------------------
__device__ __align__(16) __nv_bfloat16 g_xhi[MBIG * D];
__device__ __align__(16) __nv_bfloat16 g_xlo[MBIG * D];
__device__ __align__(16) __nv_bfloat16 g_yhi[T * D];
__device__ __align__(16) __nv_bfloat16 g_ylo[T * D];
__device__ __align__(16) __nv_bfloat16 g_wqt_hi[D * D];  // transposed: [n][k]
__device__ __align__(16) __nv_bfloat16 g_wqt_lo[D * D];
__device__ __align__(16) __nv_bfloat16 g_wkt_hi[D * D];
__device__ __align__(16) __nv_bfloat16 g_wkt_lo[D * D];
__device__ float g_wvsum[D];
__device__ float g_c[T * D];
__device__ float g_S[T * D];
__device__ float g_carry[SCAN_P * D];
__device__ float g_pre[SCAN_P * D];

// ---------------------------------------------------------------------------
// Helpers (baseline PTX only — no sm_103a-gated instructions)
// ---------------------------------------------------------------------------
__device__ __forceinline__ uint32_t smem_u32(const void* p) {
    uint32_t a;
    asm("{ .reg .u64 t; cvta.to.shared.u64 t, %1; cvt.u32.u64 %0, t; }"
        : "=r"(a) : "l"(p));
    return a;
}

__device__ __forceinline__ void cp16(uint32_t s, const void* g) {
    asm volatile("cp.async.cg.shared.global [%0], [%1], 16;"
                 :: "r"(s), "l"(g) : "memory");
}
__device__ __forceinline__ void cp_commit() {
    asm volatile("cp.async.commit_group;" ::: "memory");
}
template <int N>
__device__ __forceinline__ void cp_wait() {
    asm volatile("cp.async.wait_group %0;" :: "n"(N) : "memory");
}

#define LDSM_X4(r0, r1, r2, r3, addr) \
    asm volatile("ldmatrix.sync.aligned.m8n8.x4.shared.b16 {%0,%1,%2,%3}, [%4];" \
                 : "=r"(r0), "=r"(r1), "=r"(r2), "=r"(r3) : "r"(addr))

#define MMA_BF16(c, a, b) \
    asm volatile("mma.sync.aligned.m16n8k16.row.col.f32.bf16.bf16.f32 " \
                 "{%0,%1,%2,%3}, {%4,%5,%6,%7}, {%8,%9}, {%0,%1,%2,%3};" \
                 : "+f"((c)[0]), "+f"((c)[1]), "+f"((c)[2]), "+f"((c)[3]) \
                 : "r"((a)[0]), "r"((a)[1]), "r"((a)[2]), "r"((a)[3]), \
                   "r"((b)[0]), "r"((b)[1]))

// ---------------------------------------------------------------------------
// Kernel A: wv_sum[i] = sum_j Wv[i][j]
// ---------------------------------------------------------------------------
__global__ void wvsum_kernel(const float* __restrict__ Wv) {
    int i = threadIdx.x;
    float s = 0.f;
#pragma unroll 8
    for (int j = 0; j < D; ++j) s += Wv[i * D + j];
    g_wvsum[i] = s;
}

// ---------------------------------------------------------------------------
// Kernel W: split + transpose Wq and Wk into bf16 hi/lo, [n][k] layout.
// ---------------------------------------------------------------------------
__global__ void wconv_kernel(const float* __restrict__ Wq,
                             const float* __restrict__ Wk) {
    const float* W = blockIdx.x ? Wk : Wq;
    __nv_bfloat16* hi = blockIdx.x ? g_wkt_hi : g_wqt_hi;
    __nv_bfloat16* lo = blockIdx.x ? g_wkt_lo : g_wqt_lo;
    const int n  = blockIdx.y * 32 + (threadIdx.x & 31);
    const int k0 = (threadIdx.x >> 5) * 32;
#pragma unroll 4
    for (int kk = 0; kk < 32; ++kk) {
        const int k = k0 + kk;
        float v = W[k * D + n];
        __nv_bfloat16 h = __float2bfloat16_rn(v);
        hi[n * D + k] = h;
        lo[n * D + k] = __float2bfloat16_rn(v - __bfloat162float(h));
    }
}

// ---------------------------------------------------------------------------
// Kernel B: per-t fold over batch + x/y bf16 hi/lo splits.
// ---------------------------------------------------------------------------
__global__ void y_kernel(const float* __restrict__ x) {
    const int t = blockIdx.x;
    const int d = threadIdx.x;
    __shared__ float xs[B][D];
    __shared__ float wvs[D];
    __shared__ float vs[B];

    wvs[d] = g_wvsum[d];
#pragma unroll
    for (int b = 0; b < B; ++b)
        xs[b][d] = x[((size_t)b * T + t) * D + d];
    __syncthreads();

#pragma unroll
    for (int b = 0; b < B; ++b) {
        float v = xs[b][d];
        __nv_bfloat16 h = __float2bfloat16_rn(v);
        const size_t o = ((size_t)b * T + t) * D + d;
        g_xhi[o] = h;
        g_xlo[o] = __float2bfloat16_rn(v - __bfloat162float(h));
    }

    const int warp = d >> 5, lane = d & 31;
#pragma unroll
    for (int bb = 0; bb < 2; ++bb) {
        const int b = warp * 2 + bb;
        float p = 0.f;
#pragma unroll
        for (int i = 0; i < D / 32; ++i)
            p += xs[b][lane + 32 * i] * wvs[lane + 32 * i];
#pragma unroll
        for (int o = 16; o > 0; o >>= 1)
            p += __shfl_xor_sync(0xffffffffu, p, o);
        if (lane == 0) vs[b] = p;
    }
    __syncthreads();

    float acc = 0.f;
#pragma unroll
    for (int b = 0; b < B; ++b)
        acc += vs[b] * xs[b][d];
    __nv_bfloat16 h = __float2bfloat16_rn(acc);
    g_yhi[t * D + d] = h;
    g_ylo[t * D + d] = __float2bfloat16_rn(acc - __bfloat162float(h));
}

// ---------------------------------------------------------------------------
// Blocked decay scan
// ---------------------------------------------------------------------------
__global__ __launch_bounds__(256) void scan_local_kernel() {
    const int p = blockIdx.x, d = threadIdx.x;
    float v[SCAN_L];
#pragma unroll
    for (int i = 0; i < SCAN_L; ++i) {
        const int t = p * SCAN_L + i;
        v[i] = (t == 0) ? 0.f : g_c[t * D + d];
    }
    float r = 0.f;
#pragma unroll
    for (int i = 0; i < SCAN_L; ++i) {
        r = GAMMA * r + v[i];
        v[i] = r;
    }
#pragma unroll
    for (int i = 0; i < SCAN_L; ++i)
        g_S[(p * SCAN_L + i) * D + d] = v[i];
    g_carry[p * D + d] = r;
}

__global__ __launch_bounds__(256) void scan_carry_kernel() {
    const int d = threadIdx.x;
    float c[SCAN_P];
#pragma unroll
    for (int p = 0; p < SCAN_P; ++p)
        c[p] = g_carry[p * D + d];
    float r = 0.f;
#pragma unroll
    for (int p = 0; p < SCAN_P; ++p) {
        g_pre[p * D + d] = r;
        r = c[p] + GAMMA32 * r;
    }
}

__global__ __launch_bounds__(256) void scan_combine_kernel() {
    const int p = blockIdx.x, d = threadIdx.x;
    const float pre = g_pre[p * D + d];
    float v[SCAN_L];
#pragma unroll
    for (int i = 0; i < SCAN_L; ++i)
        v[i] = g_S[(p * SCAN_L + i) * D + d];
    float gp = GAMMA;
#pragma unroll
    for (int i = 0; i < SCAN_L; ++i) {
        v[i] += gp * pre;
        gp *= GAMMA;
    }
#pragma unroll
    for (int i = 0; i < SCAN_L; ++i)
        g_S[(p * SCAN_L + i) * D + d] = v[i];
    if (p == 0)
        g_S[d] = v[1];   // S[0] := r[1]
}

// ---------------------------------------------------------------------------
// Warp-MMA GEMM (legacy HMMA path, compiles for plain sm_103):
//   out[m, 0:256] = sum_k A[m,k] * Wt[n,k]   via 3-term bf16 split.
// BM=128, BN=128, BK=32, 8 warps (2x4), warp tile 64x32, m16n8k16 bf16.
// SMEM: 2 stages x {Ahi, Alo, Bhi, Blo} 128x32 bf16 tiles (8KB each) = 64KB.
// 16B-chunk XOR swizzle: chunk' = chunk ^ ((row>>1)&3)  (conflict-free LDSM).
// ---------------------------------------------------------------------------
constexpr int GEMM_SMEM = 65536;

template <bool SCALED>
__global__ __launch_bounds__(256, 2)
void mma_gemm(float* __restrict__ Cout_arg) {
    extern __shared__ char smem[];
    const uint32_t smem_u = smem_u32(smem);

    const int tid  = threadIdx.x;
    const int wid  = tid >> 5;
    const int lane = tid & 31;
    const int wm = (wid >> 2) * 64;   // warp M offset within 128
    const int wn = (wid & 3) * 32;    // warp N offset within 128

    const int bm = blockIdx.x * 128;
    const int bn = blockIdx.y * 128;

    const __nv_bfloat16* const Ahi = (SCALED ? g_xhi : g_yhi) + (size_t)bm * D;
    const __nv_bfloat16* const Alo = (SCALED ? g_xlo : g_ylo) + (size_t)bm * D;
    const __nv_bfloat16* const Bhi = (SCALED ? g_wqt_hi : g_wkt_hi) + (size_t)bn * D;
    const __nv_bfloat16* const Blo = (SCALED ? g_wqt_lo : g_wkt_lo) + (size_t)bn * D;
    float* const Cout = SCALED ? Cout_arg : g_c;

    // stage layout: Ahi @0, Alo @8192, Bhi @16384, Blo @24576 (per 32KB stage)
    const int ld_r  = tid >> 2;       // row 0..63 (x2 per tile)
    const int ld_ch = tid & 3;        // 16B chunk 0..3

    auto load_stage = [&](int stg, int chunk) {
        const int kc = chunk * 32;
        const uint32_t sb = smem_u + stg * 32768;
        const __nv_bfloat16* srcs[4] = { Ahi, Alo, Bhi, Blo };
#pragma unroll
        for (int t4 = 0; t4 < 4; ++t4) {
            const uint32_t tb = sb + t4 * 8192;
#pragma unroll
            for (int j = 0; j < 2; ++j) {
                const int r = ld_r + j * 64;
                const uint32_t s = tb + r * 64 + ((ld_ch ^ ((r >> 1) & 3)) << 4);
                cp16(s, srcs[t4] + (size_t)r * D + kc + ld_ch * 8);
            }
        }
    };

    // per-lane ldmatrix row/koct components
    const int laneA_r = ((lane & 8) ? 8 : 0) + (lane & 7);
    const int laneA_k = (lane & 16) ? 1 : 0;
    const int mi = lane >> 3;
    const int laneB_ns = mi >> 1;   // n-octet within pair
    const int laneB_k  = mi & 1;
    const int laneB_r  = lane & 7;

    float acc[4][4][4];
#pragma unroll
    for (int a = 0; a < 4; ++a)
#pragma unroll
        for (int b = 0; b < 4; ++b)
#pragma unroll
            for (int q = 0; q < 4; ++q) acc[a][b][q] = 0.f;

    load_stage(0, 0);
    cp_commit();

#pragma unroll 1
    for (int chunk = 0; chunk < 8; ++chunk) {
        const int stg = chunk & 1;
        if (chunk < 7) {
            load_stage(stg ^ 1, chunk + 1);
            cp_commit();
            cp_wait<1>();
        } else {
            cp_wait<0>();
        }
        __syncthreads();

        const uint32_t sb = smem_u + stg * 32768;
#pragma unroll
        for (int term = 0; term < 3; ++term) {
            const uint32_t abase = sb + (term == 1 ? 8192 : 0);
            const uint32_t bbase = sb + 16384 + (term == 2 ? 8192 : 0);
#pragma unroll
            for (int ks = 0; ks < 32; ks += 16) {
                uint32_t aR[4][4], bR[4][2];
#pragma unroll
                for (int mt = 0; mt < 4; ++mt) {
                    const int R = wm + mt * 16 + laneA_r;
                    const int ko = (ks >> 3) + laneA_k;
                    const uint32_t ad =
                        abase + R * 64 + ((ko ^ ((R >> 1) & 3)) << 4);
                    LDSM_X4(aR[mt][0], aR[mt][1], aR[mt][2], aR[mt][3], ad);
                }
#pragma unroll
                for (int g = 0; g < 2; ++g) {
                    const int R = wn + (2 * g + laneB_ns) * 8 + laneB_r;
                    const int ko = (ks >> 3) + laneB_k;
                    const uint32_t bd =
                        bbase + R * 64 + ((ko ^ ((R >> 1) & 3)) << 4);
                    LDSM_X4(bR[2 * g][0], bR[2 * g][1],
                            bR[2 * g + 1][0], bR[2 * g + 1][1], bd);
                }
#pragma unroll
                for (int mt = 0; mt < 4; ++mt)
#pragma unroll
                    for (int nt = 0; nt < 4; ++nt)
                        MMA_BF16(acc[mt][nt], aR[mt], bR[nt]);
            }
        }
        __syncthreads();
    }

    // Epilogue: fragment (mt,nt): rows R0=.., R0+8; cols Cb, Cb+1.
    const int rbase = bm + wm + (lane >> 2);
    const int cbase = bn + wn + 2 * (lane & 3);
#pragma unroll
    for (int mt = 0; mt < 4; ++mt) {
        const int R0 = rbase + mt * 16;
        const int R1 = R0 + 8;
        const int t0 = R0 & (T - 1);
        const int t1 = R1 & (T - 1);
#pragma unroll
        for (int nt = 0; nt < 4; ++nt) {
            const int C = cbase + nt * 8;
            float2 v01, v23;
            v01.x = acc[mt][nt][0];
            v01.y = acc[mt][nt][1];
            v23.x = acc[mt][nt][2];
            v23.y = acc[mt][nt][3];
            if (SCALED) {
                const float s0 = g_S[(size_t)C * T + t0];
                const float s1 = g_S[(size_t)(C + 1) * T + t0];
                const float s2 = g_S[(size_t)C * T + t1];
                const float s3 = g_S[(size_t)(C + 1) * T + t1];
                v01.x *= s0; v01.y *= s1;
                v23.x *= s2; v23.y *= s3;
            }
            *reinterpret_cast<float2*>(&Cout[(size_t)R0 * D + C]) = v01;
            *reinterpret_cast<float2*>(&Cout[(size_t)R1 * D + C]) = v23;
        }
    }
}

// ---------------------------------------------------------------------------
extern "C" void kernel_launch(void* const* d_in, const int* in_sizes, int n_in,
                              void* d_out, int out_size) {
    const float* x  = (const float*)d_in[0];
    const float* Wq = (const float*)d_in[1];
    const float* Wk = (const float*)d_in[2];
    const float* Wv = (const float*)d_in[3];
    float* out = (float*)d_out;

    cudaFuncSetAttribute(mma_gemm<false>,
                         cudaFuncAttributeMaxDynamicSharedMemorySize, GEMM_SMEM);
    cudaFuncSetAttribute(mma_gemm<true>,
                         cudaFuncAttributeMaxDynamicSharedMemorySize, GEMM_SMEM);

    // A: row-sums of Wv
    wvsum_kernel<<<1, 256>>>(Wv);
    // W: split+transpose Wq/Wk into bf16 hi/lo
    wconv_kernel<<<dim3(2, 8), 256>>>(Wq, Wk);
    // B: vsum fold + y (also emits x hi/lo split)
    y_kernel<<<T, 256>>>(x);
    // C: c = y @ Wk via warp-MMA
    mma_gemm<false><<<dim3(T / 128, 2), 256, GEMM_SMEM>>>(nullptr);
    // D: blocked decay scan -> S
    scan_local_kernel<<<SCAN_P, 256>>>();
    scan_carry_kernel<<<1, 256>>>();
    scan_combine_kernel<<<SCAN_P, 256>>>();
    // E: out = S2 .* (x @ Wq) via warp-MMA
    mma_gemm<true><<<dim3(MBIG / 128, 2), 256, GEMM_SMEM>>>(out);
}

// round 11
// speedup vs baseline: 7.8439x; 1.3907x over previous
#include <cuda_runtime.h>
#include <cuda_bf16.h>
#include <cstdint>

// Problem constants
constexpr int B = 16;
constexpr int T = 2048;
constexpr int D = 256;
constexpr int MBIG = B * T;          // 32768
constexpr int SCAN_L = 32;
constexpr int SCAN_P = T / SCAN_L;   // 64
constexpr float GAMMA   = 0.9f;
constexpr float GAMMA32 = 0.03433683820292512f;  // 0.9^32

// ---------------------------------------------------------------------------
// Static device scratch
// ---------------------------------------------------------------------------
__device__ __align__(16) __nv_bfloat16 g_xhi[MBIG * D];
__device__ __align__(16) __nv_bfloat16 g_xlo[MBIG * D];
__device__ __align__(16) __nv_bfloat16 g_yhi[T * D];
__device__ __align__(16) __nv_bfloat16 g_ylo[T * D];
__device__ __align__(16) __nv_bfloat16 g_wqt_hi[D * D];  // transposed: [n][k]
__device__ __align__(16) __nv_bfloat16 g_wqt_lo[D * D];
__device__ __align__(16) __nv_bfloat16 g_wkt_hi[D * D];
__device__ __align__(16) __nv_bfloat16 g_wkt_lo[D * D];
__device__ float g_wvsum[D];
__device__ float g_c[T * D];
__device__ float g_S[T * D];
__device__ float g_carry[SCAN_P * D];
__device__ float g_pre[SCAN_P * D];

// ---------------------------------------------------------------------------
// Helpers (baseline PTX only)
// ---------------------------------------------------------------------------
__device__ __forceinline__ uint32_t smem_u32(const void* p) {
    uint32_t a;
    asm("{ .reg .u64 t; cvta.to.shared.u64 t, %1; cvt.u32.u64 %0, t; }"
        : "=r"(a) : "l"(p));
    return a;
}

__device__ __forceinline__ void cp16(uint32_t s, const void* g) {
    asm volatile("cp.async.cg.shared.global [%0], [%1], 16;"
                 :: "r"(s), "l"(g) : "memory");
}
__device__ __forceinline__ void cp_commit() {
    asm volatile("cp.async.commit_group;" ::: "memory");
}
template <int N>
__device__ __forceinline__ void cp_wait() {
    asm volatile("cp.async.wait_group %0;" :: "n"(N) : "memory");
}

#define LDSM_X4(r0, r1, r2, r3, addr) \
    asm volatile("ldmatrix.sync.aligned.m8n8.x4.shared.b16 {%0,%1,%2,%3}, [%4];" \
                 : "=r"(r0), "=r"(r1), "=r"(r2), "=r"(r3) : "r"(addr))

#define MMA_BF16(c, a, b) \
    asm volatile("mma.sync.aligned.m16n8k16.row.col.f32.bf16.bf16.f32 " \
                 "{%0,%1,%2,%3}, {%4,%5,%6,%7}, {%8,%9}, {%0,%1,%2,%3};" \
                 : "+f"((c)[0]), "+f"((c)[1]), "+f"((c)[2]), "+f"((c)[3]) \
                 : "r"((a)[0]), "r"((a)[1]), "r"((a)[2]), "r"((a)[3]), \
                   "r"((b)[0]), "r"((b)[1]))

// ---------------------------------------------------------------------------
// Kernel A: wv_sum[i] = sum_j Wv[i][j]   (grid 8 x 256, coalesced)
// ---------------------------------------------------------------------------
__global__ void wvsum_kernel(const float* __restrict__ Wv) {
    const int warp = threadIdx.x >> 5, lane = threadIdx.x & 31;
    const int row0 = blockIdx.x * 32 + warp * 4;
#pragma unroll
    for (int rr = 0; rr < 4; ++rr) {
        const int row = row0 + rr;
        float s = 0.f;
#pragma unroll
        for (int i = 0; i < 8; ++i)
            s += Wv[row * D + lane + 32 * i];
#pragma unroll
        for (int o = 16; o > 0; o >>= 1)
            s += __shfl_xor_sync(0xffffffffu, s, o);
        if (lane == 0) g_wvsum[row] = s;
    }
}

// ---------------------------------------------------------------------------
// Kernel W: split + transpose Wq and Wk into bf16 hi/lo, [n][k] layout.
// ---------------------------------------------------------------------------
__global__ void wconv_kernel(const float* __restrict__ Wq,
                             const float* __restrict__ Wk) {
    const float* W = blockIdx.x ? Wk : Wq;
    __nv_bfloat16* hi = blockIdx.x ? g_wkt_hi : g_wqt_hi;
    __nv_bfloat16* lo = blockIdx.x ? g_wkt_lo : g_wqt_lo;
    const int n  = blockIdx.y * 32 + (threadIdx.x & 31);
    const int k0 = (threadIdx.x >> 5) * 32;
#pragma unroll 4
    for (int kk = 0; kk < 32; ++kk) {
        const int k = k0 + kk;
        float v = W[k * D + n];
        __nv_bfloat16 h = __float2bfloat16_rn(v);
        hi[n * D + k] = h;
        lo[n * D + k] = __float2bfloat16_rn(v - __bfloat162float(h));
    }
}

// ---------------------------------------------------------------------------
// Kernel B: per-t fold over batch + x/y bf16 hi/lo splits.
// ---------------------------------------------------------------------------
__global__ void y_kernel(const float* __restrict__ x) {
    const int t = blockIdx.x;
    const int d = threadIdx.x;
    __shared__ float xs[B][D];
    __shared__ float wvs[D];
    __shared__ float vs[B];

    wvs[d] = g_wvsum[d];
#pragma unroll
    for (int b = 0; b < B; ++b)
        xs[b][d] = x[((size_t)b * T + t) * D + d];
    __syncthreads();

#pragma unroll
    for (int b = 0; b < B; ++b) {
        float v = xs[b][d];
        __nv_bfloat16 h = __float2bfloat16_rn(v);
        const size_t o = ((size_t)b * T + t) * D + d;
        g_xhi[o] = h;
        g_xlo[o] = __float2bfloat16_rn(v - __bfloat162float(h));
    }

    const int warp = d >> 5, lane = d & 31;
#pragma unroll
    for (int bb = 0; bb < 2; ++bb) {
        const int b = warp * 2 + bb;
        float p = 0.f;
#pragma unroll
        for (int i = 0; i < D / 32; ++i)
            p += xs[b][lane + 32 * i] * wvs[lane + 32 * i];
#pragma unroll
        for (int o = 16; o > 0; o >>= 1)
            p += __shfl_xor_sync(0xffffffffu, p, o);
        if (lane == 0) vs[b] = p;
    }
    __syncthreads();

    float acc = 0.f;
#pragma unroll
    for (int b = 0; b < B; ++b)
        acc += vs[b] * xs[b][d];
    __nv_bfloat16 h = __float2bfloat16_rn(acc);
    g_yhi[t * D + d] = h;
    g_ylo[t * D + d] = __float2bfloat16_rn(acc - __bfloat162float(h));
}

// ---------------------------------------------------------------------------
// Blocked decay scan
// ---------------------------------------------------------------------------
__global__ __launch_bounds__(256) void scan_local_kernel() {
    const int p = blockIdx.x, d = threadIdx.x;
    float v[SCAN_L];
#pragma unroll
    for (int i = 0; i < SCAN_L; ++i) {
        const int t = p * SCAN_L + i;
        v[i] = (t == 0) ? 0.f : g_c[t * D + d];
    }
    float r = 0.f;
#pragma unroll
    for (int i = 0; i < SCAN_L; ++i) {
        r = GAMMA * r + v[i];
        v[i] = r;
    }
#pragma unroll
    for (int i = 0; i < SCAN_L; ++i)
        g_S[(p * SCAN_L + i) * D + d] = v[i];
    g_carry[p * D + d] = r;
}

__global__ __launch_bounds__(256) void scan_carry_kernel() {
    const int d = threadIdx.x;
    float c[SCAN_P];
#pragma unroll
    for (int p = 0; p < SCAN_P; ++p)
        c[p] = g_carry[p * D + d];
    float r = 0.f;
#pragma unroll
    for (int p = 0; p < SCAN_P; ++p) {
        g_pre[p * D + d] = r;
        r = c[p] + GAMMA32 * r;
    }
}

__global__ __launch_bounds__(256) void scan_combine_kernel() {
    const int p = blockIdx.x, d = threadIdx.x;
    const float pre = g_pre[p * D + d];
    float v[SCAN_L];
#pragma unroll
    for (int i = 0; i < SCAN_L; ++i)
        v[i] = g_S[(p * SCAN_L + i) * D + d];
    float gp = GAMMA;
#pragma unroll
    for (int i = 0; i < SCAN_L; ++i) {
        v[i] += gp * pre;
        gp *= GAMMA;
    }
#pragma unroll
    for (int i = 0; i < SCAN_L; ++i)
        g_S[(p * SCAN_L + i) * D + d] = v[i];
    if (p == 0)
        g_S[d] = v[1];   // S[0] := r[1]
}

// ---------------------------------------------------------------------------
// Warp-MMA GEMM (legacy HMMA path), templated on fragment counts:
//   warp grid fixed 2x4; BM = 32*MT, BN = 32*NT; BK=32; 3-stage cp.async.
// 16B-chunk XOR swizzle: chunk' = chunk ^ ((row>>1)&3)  (conflict-free LDSM).
// ---------------------------------------------------------------------------
template <bool SCALED, int MT, int NT>
__global__ __launch_bounds__(256, 2)
void mma_gemm(float* __restrict__ Cout_arg) {
    constexpr int BM = 32 * MT;
    constexpr int BN = 32 * NT;
    constexpr int ASZ = BM * 64;           // one A tile (BMx32 bf16), bytes
    constexpr int BSZ = BN * 64;
    constexpr int STAGE = 2 * (ASZ + BSZ); // Ahi, Alo, Bhi, Blo

    extern __shared__ char smem[];
    const uint32_t smem_u = smem_u32(smem);

    const int tid  = threadIdx.x;
    const int wid  = tid >> 5;
    const int lane = tid & 31;
    const int wm = (wid >> 2) * (MT * 16);   // warp M offset
    const int wn = (wid & 3) * (NT * 8);     // warp N offset

    const int bm = blockIdx.x * BM;
    const int bn = blockIdx.y * BN;

    const __nv_bfloat16* const Ahi = (SCALED ? g_xhi : g_yhi) + (size_t)bm * D;
    const __nv_bfloat16* const Alo = (SCALED ? g_xlo : g_ylo) + (size_t)bm * D;
    const __nv_bfloat16* const Bhi = (SCALED ? g_wqt_hi : g_wkt_hi) + (size_t)bn * D;
    const __nv_bfloat16* const Blo = (SCALED ? g_wqt_lo : g_wkt_lo) + (size_t)bn * D;
    float* const Cout = SCALED ? Cout_arg : g_c;

    auto load_stage = [&](int stg, int chunk) {
        const int kc = chunk * 32;
        const uint32_t sb = smem_u + stg * STAGE;
#pragma unroll
        for (int t4 = 0; t4 < 2; ++t4) {          // A hi, A lo
            const uint32_t tb = sb + t4 * ASZ;
            const __nv_bfloat16* src = t4 ? Alo : Ahi;
#pragma unroll
            for (int idx = 0; idx < BM * 4 / 256; ++idx) {
                const int q = tid + idx * 256;
                const int r = q >> 2, ch = q & 3;
                const uint32_t s = tb + r * 64 + ((ch ^ ((r >> 1) & 3)) << 4);
                cp16(s, src + (size_t)r * D + kc + ch * 8);
            }
        }
#pragma unroll
        for (int t4 = 0; t4 < 2; ++t4) {          // B hi, B lo
            const uint32_t tb = sb + 2 * ASZ + t4 * BSZ;
            const __nv_bfloat16* src = t4 ? Blo : Bhi;
#pragma unroll
            for (int idx = 0; idx < BN * 4 / 256; ++idx) {
                const int q = tid + idx * 256;
                const int r = q >> 2, ch = q & 3;
                const uint32_t s = tb + r * 64 + ((ch ^ ((r >> 1) & 3)) << 4);
                cp16(s, src + (size_t)r * D + kc + ch * 8);
            }
        }
    };

    // per-lane ldmatrix row/koct components
    const int laneA_r = ((lane & 8) ? 8 : 0) + (lane & 7);
    const int laneA_k = (lane & 16) ? 1 : 0;
    const int mi = lane >> 3;
    const int laneB_ns = mi >> 1;
    const int laneB_k  = mi & 1;
    const int laneB_r  = lane & 7;

    float acc[MT][NT][4];
#pragma unroll
    for (int a = 0; a < MT; ++a)
#pragma unroll
        for (int b = 0; b < NT; ++b)
#pragma unroll
            for (int q = 0; q < 4; ++q) acc[a][b][q] = 0.f;

    load_stage(0, 0);
    cp_commit();
    load_stage(1, 1);
    cp_commit();

#pragma unroll 1
    for (int chunk = 0; chunk < 8; ++chunk) {
        const int stg = chunk % 3;
        if (chunk + 2 < 8) {
            load_stage((chunk + 2) % 3, chunk + 2);
            cp_commit();
            cp_wait<2>();
        } else if (chunk + 1 < 8) {
            cp_wait<1>();
        } else {
            cp_wait<0>();
        }
        __syncthreads();

        const uint32_t sb = smem_u + stg * STAGE;
#pragma unroll
        for (int term = 0; term < 3; ++term) {
            const uint32_t abase = sb + (term == 1 ? ASZ : 0);
            const uint32_t bbase = sb + 2 * ASZ + (term == 2 ? BSZ : 0);
#pragma unroll
            for (int ks = 0; ks < 32; ks += 16) {
                uint32_t aR[MT][4], bR[NT][2];
#pragma unroll
                for (int mt = 0; mt < MT; ++mt) {
                    const int R = wm + mt * 16 + laneA_r;
                    const int ko = (ks >> 3) + laneA_k;
                    const uint32_t ad =
                        abase + R * 64 + ((ko ^ ((R >> 1) & 3)) << 4);
                    LDSM_X4(aR[mt][0], aR[mt][1], aR[mt][2], aR[mt][3], ad);
                }
#pragma unroll
                for (int g = 0; g < NT / 2; ++g) {
                    const int R = wn + (2 * g + laneB_ns) * 8 + laneB_r;
                    const int ko = (ks >> 3) + laneB_k;
                    const uint32_t bd =
                        bbase + R * 64 + ((ko ^ ((R >> 1) & 3)) << 4);
                    LDSM_X4(bR[2 * g][0], bR[2 * g][1],
                            bR[2 * g + 1][0], bR[2 * g + 1][1], bd);
                }
#pragma unroll
                for (int mt = 0; mt < MT; ++mt)
#pragma unroll
                    for (int nt = 0; nt < NT; ++nt)
                        MMA_BF16(acc[mt][nt], aR[mt], bR[nt]);
            }
        }
        __syncthreads();
    }

    // Epilogue
    const int rbase = bm + wm + (lane >> 2);
    const int cbase = bn + wn + 2 * (lane & 3);
#pragma unroll
    for (int mt = 0; mt < MT; ++mt) {
        const int R0 = rbase + mt * 16;
        const int R1 = R0 + 8;
        const int t0 = R0 & (T - 1);
        const int t1 = R1 & (T - 1);
#pragma unroll
        for (int nt = 0; nt < NT; ++nt) {
            const int C = cbase + nt * 8;
            float2 v01, v23;
            v01.x = acc[mt][nt][0];
            v01.y = acc[mt][nt][1];
            v23.x = acc[mt][nt][2];
            v23.y = acc[mt][nt][3];
            if (SCALED) {
                const float s0 = g_S[(size_t)C * T + t0];
                const float s1 = g_S[(size_t)(C + 1) * T + t0];
                const float s2 = g_S[(size_t)C * T + t1];
                const float s3 = g_S[(size_t)(C + 1) * T + t1];
                v01.x *= s0; v01.y *= s1;
                v23.x *= s2; v23.y *= s3;
            }
            *reinterpret_cast<float2*>(&Cout[(size_t)R0 * D + C]) = v01;
            *reinterpret_cast<float2*>(&Cout[(size_t)R1 * D + C]) = v23;
        }
    }
}

constexpr int SMEM_BIG   = 3 * 2 * (128 * 64 + 128 * 64);  // 98304
constexpr int SMEM_SMALL = 3 * 2 * (64 * 64 + 64 * 64);    // 49152

// ---------------------------------------------------------------------------
extern "C" void kernel_launch(void* const* d_in, const int* in_sizes, int n_in,
                              void* d_out, int out_size) {
    const float* x  = (const float*)d_in[0];
    const float* Wq = (const float*)d_in[1];
    const float* Wk = (const float*)d_in[2];
    const float* Wv = (const float*)d_in[3];
    float* out = (float*)d_out;

    cudaFuncSetAttribute(mma_gemm<false, 2, 2>,
                         cudaFuncAttributeMaxDynamicSharedMemorySize, SMEM_SMALL);
    cudaFuncSetAttribute(mma_gemm<true, 4, 4>,
                         cudaFuncAttributeMaxDynamicSharedMemorySize, SMEM_BIG);

    // A: row-sums of Wv (coalesced)
    wvsum_kernel<<<8, 256>>>(Wv);
    // W: split+transpose Wq/Wk into bf16 hi/lo
    wconv_kernel<<<dim3(2, 8), 256>>>(Wq, Wk);
    // B: vsum fold + y (also emits x hi/lo split)
    y_kernel<<<T, 256>>>(x);
    // C: c = y @ Wk via warp-MMA, 64x64 tiles (128 CTAs)
    mma_gemm<false, 2, 2><<<dim3(T / 64, D / 64), 256, SMEM_SMALL>>>(nullptr);
    // D: blocked decay scan -> S
    scan_local_kernel<<<SCAN_P, 256>>>();
    scan_carry_kernel<<<1, 256>>>();
    scan_combine_kernel<<<SCAN_P, 256>>>();
    // E: out = S2 .* (x @ Wq) via warp-MMA, 128x128 tiles
    mma_gemm<true, 4, 4><<<dim3(MBIG / 128, D / 128), 256, SMEM_BIG>>>(out);
}

// round 12
// speedup vs baseline: 8.5311x; 1.0876x over previous
#include <cuda_runtime.h>
#include <cuda_bf16.h>
#include <cstdint>

// Problem constants
constexpr int B = 16;
constexpr int T = 2048;
constexpr int D = 256;
constexpr int MBIG = B * T;          // 32768
constexpr int SCAN_L = 32;
constexpr int SCAN_P = T / SCAN_L;   // 64
constexpr float GAMMA   = 0.9f;
constexpr float GAMMA32 = 0.03433683820292512f;  // 0.9^32

// ---------------------------------------------------------------------------
// Static device scratch
// ---------------------------------------------------------------------------
__device__ __align__(16) __nv_bfloat16 g_xhi[MBIG * D];
__device__ __align__(16) __nv_bfloat16 g_xlo[MBIG * D];
__device__ __align__(16) __nv_bfloat16 g_yhi[T * D];
__device__ __align__(16) __nv_bfloat16 g_ylo[T * D];
__device__ __align__(16) __nv_bfloat16 g_wqt_hi[D * D];  // transposed: [n][k]
__device__ __align__(16) __nv_bfloat16 g_wqt_lo[D * D];
__device__ __align__(16) __nv_bfloat16 g_wkt_hi[D * D];
__device__ __align__(16) __nv_bfloat16 g_wkt_lo[D * D];
__device__ float g_wvsum[D];
__device__ float g_c[T * D];
__device__ float g_S[T * D];
__device__ float g_carry[SCAN_P * D];
__device__ float g_pre[SCAN_P * D];

// ---------------------------------------------------------------------------
// Helpers (baseline PTX only)
// ---------------------------------------------------------------------------
__device__ __forceinline__ uint32_t smem_u32(const void* p) {
    uint32_t a;
    asm("{ .reg .u64 t; cvta.to.shared.u64 t, %1; cvt.u32.u64 %0, t; }"
        : "=r"(a) : "l"(p));
    return a;
}

__device__ __forceinline__ void cp16(uint32_t s, const void* g) {
    asm volatile("cp.async.cg.shared.global [%0], [%1], 16;"
                 :: "r"(s), "l"(g) : "memory");
}
__device__ __forceinline__ void cp_commit() {
    asm volatile("cp.async.commit_group;" ::: "memory");
}
template <int N>
__device__ __forceinline__ void cp_wait() {
    asm volatile("cp.async.wait_group %0;" :: "n"(N) : "memory");
}

#define LDSM_X4(r0, r1, r2, r3, addr) \
    asm volatile("ldmatrix.sync.aligned.m8n8.x4.shared.b16 {%0,%1,%2,%3}, [%4];" \
                 : "=r"(r0), "=r"(r1), "=r"(r2), "=r"(r3) : "r"(addr))

#define MMA_BF16(c, a, b) \
    asm volatile("mma.sync.aligned.m16n8k16.row.col.f32.bf16.bf16.f32 " \
                 "{%0,%1,%2,%3}, {%4,%5,%6,%7}, {%8,%9}, {%0,%1,%2,%3};" \
                 : "+f"((c)[0]), "+f"((c)[1]), "+f"((c)[2]), "+f"((c)[3]) \
                 : "r"((a)[0]), "r"((a)[1]), "r"((a)[2]), "r"((a)[3]), \
                   "r"((b)[0]), "r"((b)[1]))

// ---------------------------------------------------------------------------
// Kernel A: wv_sum[i] = sum_j Wv[i][j]   (grid 8 x 256, coalesced)
// ---------------------------------------------------------------------------
__global__ void wvsum_kernel(const float* __restrict__ Wv) {
    const int warp = threadIdx.x >> 5, lane = threadIdx.x & 31;
    const int row0 = blockIdx.x * 32 + warp * 4;
#pragma unroll
    for (int rr = 0; rr < 4; ++rr) {
        const int row = row0 + rr;
        float s = 0.f;
#pragma unroll
        for (int i = 0; i < 8; ++i)
            s += Wv[row * D + lane + 32 * i];
#pragma unroll
        for (int o = 16; o > 0; o >>= 1)
            s += __shfl_xor_sync(0xffffffffu, s, o);
        if (lane == 0) g_wvsum[row] = s;
    }
}

// ---------------------------------------------------------------------------
// Kernel W: split + transpose Wq and Wk into bf16 hi/lo, [n][k] layout.
// ---------------------------------------------------------------------------
__global__ void wconv_kernel(const float* __restrict__ Wq,
                             const float* __restrict__ Wk) {
    const float* W = blockIdx.x ? Wk : Wq;
    __nv_bfloat16* hi = blockIdx.x ? g_wkt_hi : g_wqt_hi;
    __nv_bfloat16* lo = blockIdx.x ? g_wkt_lo : g_wqt_lo;
    const int n  = blockIdx.y * 32 + (threadIdx.x & 31);
    const int k0 = (threadIdx.x >> 5) * 32;
#pragma unroll 4
    for (int kk = 0; kk < 32; ++kk) {
        const int k = k0 + kk;
        float v = W[k * D + n];
        __nv_bfloat16 h = __float2bfloat16_rn(v);
        hi[n * D + k] = h;
        lo[n * D + k] = __float2bfloat16_rn(v - __bfloat162float(h));
    }
}

// ---------------------------------------------------------------------------
// Kernel B: per-t fold over batch + x/y bf16 hi/lo splits.
// ---------------------------------------------------------------------------
__global__ void y_kernel(const float* __restrict__ x) {
    const int t = blockIdx.x;
    const int d = threadIdx.x;
    __shared__ float xs[B][D];
    __shared__ float wvs[D];
    __shared__ float vs[B];

    wvs[d] = g_wvsum[d];
#pragma unroll
    for (int b = 0; b < B; ++b)
        xs[b][d] = x[((size_t)b * T + t) * D + d];
    __syncthreads();

#pragma unroll
    for (int b = 0; b < B; ++b) {
        float v = xs[b][d];
        __nv_bfloat16 h = __float2bfloat16_rn(v);
        const size_t o = ((size_t)b * T + t) * D + d;
        g_xhi[o] = h;
        g_xlo[o] = __float2bfloat16_rn(v - __bfloat162float(h));
    }

    const int warp = d >> 5, lane = d & 31;
#pragma unroll
    for (int bb = 0; bb < 2; ++bb) {
        const int b = warp * 2 + bb;
        float p = 0.f;
#pragma unroll
        for (int i = 0; i < D / 32; ++i)
            p += xs[b][lane + 32 * i] * wvs[lane + 32 * i];
#pragma unroll
        for (int o = 16; o > 0; o >>= 1)
            p += __shfl_xor_sync(0xffffffffu, p, o);
        if (lane == 0) vs[b] = p;
    }
    __syncthreads();

    float acc = 0.f;
#pragma unroll
    for (int b = 0; b < B; ++b)
        acc += vs[b] * xs[b][d];
    __nv_bfloat16 h = __float2bfloat16_rn(acc);
    g_yhi[t * D + d] = h;
    g_ylo[t * D + d] = __float2bfloat16_rn(acc - __bfloat162float(h));
}

// ---------------------------------------------------------------------------
// Blocked decay scan
// ---------------------------------------------------------------------------
__global__ __launch_bounds__(256) void scan_local_kernel() {
    const int p = blockIdx.x, d = threadIdx.x;
    float v[SCAN_L];
#pragma unroll
    for (int i = 0; i < SCAN_L; ++i) {
        const int t = p * SCAN_L + i;
        v[i] = (t == 0) ? 0.f : g_c[t * D + d];
    }
    float r = 0.f;
#pragma unroll
    for (int i = 0; i < SCAN_L; ++i) {
        r = GAMMA * r + v[i];
        v[i] = r;
    }
#pragma unroll
    for (int i = 0; i < SCAN_L; ++i)
        g_S[(p * SCAN_L + i) * D + d] = v[i];
    g_carry[p * D + d] = r;
}

__global__ __launch_bounds__(256) void scan_carry_kernel() {
    const int d = threadIdx.x;
    float c[SCAN_P];
#pragma unroll
    for (int p = 0; p < SCAN_P; ++p)
        c[p] = g_carry[p * D + d];
    float r = 0.f;
#pragma unroll
    for (int p = 0; p < SCAN_P; ++p) {
        g_pre[p * D + d] = r;
        r = c[p] + GAMMA32 * r;
    }
}

__global__ __launch_bounds__(256) void scan_combine_kernel() {
    const int p = blockIdx.x, d = threadIdx.x;
    const float pre = g_pre[p * D + d];
    float v[SCAN_L];
#pragma unroll
    for (int i = 0; i < SCAN_L; ++i)
        v[i] = g_S[(p * SCAN_L + i) * D + d];
    float gp = GAMMA;
#pragma unroll
    for (int i = 0; i < SCAN_L; ++i) {
        v[i] += gp * pre;
        gp *= GAMMA;
    }
#pragma unroll
    for (int i = 0; i < SCAN_L; ++i)
        g_S[(p * SCAN_L + i) * D + d] = v[i];
    if (p == 0)
        g_S[d] = v[1];   // S[0] := r[1]
}

// ---------------------------------------------------------------------------
// Warp-MMA GEMM (legacy HMMA path), templated on fragment counts:
//   warp grid fixed 2x4; BM = 32*MT, BN = 32*NT; BK=32; 3-stage cp.async.
// Per-ks fragment hoist: Ahi/Alo/Bhi/Blo ldmatrix'd ONCE, reused by all 3
// split terms (hi*hi, lo*hi, hi*lo) issued back-to-back from registers.
// 16B-chunk XOR swizzle: chunk' = chunk ^ ((row>>1)&3)  (conflict-free LDSM).
// ---------------------------------------------------------------------------
template <bool SCALED, int MT, int NT>
__global__ __launch_bounds__(256, 2)
void mma_gemm(float* __restrict__ Cout_arg) {
    constexpr int BM = 32 * MT;
    constexpr int BN = 32 * NT;
    constexpr int ASZ = BM * 64;           // one A tile (BMx32 bf16), bytes
    constexpr int BSZ = BN * 64;
    constexpr int STAGE = 2 * (ASZ + BSZ); // Ahi, Alo, Bhi, Blo

    extern __shared__ char smem[];
    const uint32_t smem_u = smem_u32(smem);

    const int tid  = threadIdx.x;
    const int wid  = tid >> 5;
    const int lane = tid & 31;
    const int wm = (wid >> 2) * (MT * 16);   // warp M offset
    const int wn = (wid & 3) * (NT * 8);     // warp N offset

    const int bm = blockIdx.x * BM;
    const int bn = blockIdx.y * BN;

    const __nv_bfloat16* const Ahi = (SCALED ? g_xhi : g_yhi) + (size_t)bm * D;
    const __nv_bfloat16* const Alo = (SCALED ? g_xlo : g_ylo) + (size_t)bm * D;
    const __nv_bfloat16* const Bhi = (SCALED ? g_wqt_hi : g_wkt_hi) + (size_t)bn * D;
    const __nv_bfloat16* const Blo = (SCALED ? g_wqt_lo : g_wkt_lo) + (size_t)bn * D;
    float* const Cout = SCALED ? Cout_arg : g_c;

    auto load_stage = [&](int stg, int chunk) {
        const int kc = chunk * 32;
        const uint32_t sb = smem_u + stg * STAGE;
#pragma unroll
        for (int t4 = 0; t4 < 2; ++t4) {          // A hi, A lo
            const uint32_t tb = sb + t4 * ASZ;
            const __nv_bfloat16* src = t4 ? Alo : Ahi;
#pragma unroll
            for (int idx = 0; idx < BM * 4 / 256; ++idx) {
                const int q = tid + idx * 256;
                const int r = q >> 2, ch = q & 3;
                const uint32_t s = tb + r * 64 + ((ch ^ ((r >> 1) & 3)) << 4);
                cp16(s, src + (size_t)r * D + kc + ch * 8);
            }
        }
#pragma unroll
        for (int t4 = 0; t4 < 2; ++t4) {          // B hi, B lo
            const uint32_t tb = sb + 2 * ASZ + t4 * BSZ;
            const __nv_bfloat16* src = t4 ? Blo : Bhi;
#pragma unroll
            for (int idx = 0; idx < BN * 4 / 256; ++idx) {
                const int q = tid + idx * 256;
                const int r = q >> 2, ch = q & 3;
                const uint32_t s = tb + r * 64 + ((ch ^ ((r >> 1) & 3)) << 4);
                cp16(s, src + (size_t)r * D + kc + ch * 8);
            }
        }
    };

    // per-lane ldmatrix row/koct components
    const int laneA_r = ((lane & 8) ? 8 : 0) + (lane & 7);
    const int laneA_k = (lane & 16) ? 1 : 0;
    const int mi = lane >> 3;
    const int laneB_ns = mi >> 1;
    const int laneB_k  = mi & 1;
    const int laneB_r  = lane & 7;

    float acc[MT][NT][4];
#pragma unroll
    for (int a = 0; a < MT; ++a)
#pragma unroll
        for (int b = 0; b < NT; ++b)
#pragma unroll
            for (int q = 0; q < 4; ++q) acc[a][b][q] = 0.f;

    load_stage(0, 0);
    cp_commit();
    load_stage(1, 1);
    cp_commit();

#pragma unroll 1
    for (int chunk = 0; chunk < 8; ++chunk) {
        const int stg = chunk % 3;
        if (chunk + 2 < 8) {
            load_stage((chunk + 2) % 3, chunk + 2);
            cp_commit();
            cp_wait<2>();
        } else if (chunk + 1 < 8) {
            cp_wait<1>();
        } else {
            cp_wait<0>();
        }
        __syncthreads();

        const uint32_t sb = smem_u + stg * STAGE;
#pragma unroll
        for (int ks = 0; ks < 32; ks += 16) {
            const int ko = (ks >> 3);
            // --- hoist all fragments for this ks ---
            uint32_t aH[MT][4], aL[MT][4], bH[NT][2], bL[NT][2];
#pragma unroll
            for (int mt = 0; mt < MT; ++mt) {
                const int R = wm + mt * 16 + laneA_r;
                const int kk = ko + laneA_k;
                const uint32_t sw = R * 64 + ((kk ^ ((R >> 1) & 3)) << 4);
                LDSM_X4(aH[mt][0], aH[mt][1], aH[mt][2], aH[mt][3], sb + sw);
                LDSM_X4(aL[mt][0], aL[mt][1], aL[mt][2], aL[mt][3],
                        sb + ASZ + sw);
            }
#pragma unroll
            for (int g = 0; g < NT / 2; ++g) {
                const int R = wn + (2 * g + laneB_ns) * 8 + laneB_r;
                const int kk = ko + laneB_k;
                const uint32_t sw = R * 64 + ((kk ^ ((R >> 1) & 3)) << 4);
                LDSM_X4(bH[2 * g][0], bH[2 * g][1],
                        bH[2 * g + 1][0], bH[2 * g + 1][1], sb + 2 * ASZ + sw);
                LDSM_X4(bL[2 * g][0], bL[2 * g][1],
                        bL[2 * g + 1][0], bL[2 * g + 1][1],
                        sb + 2 * ASZ + BSZ + sw);
            }
            // --- 3 split terms from registers ---
#pragma unroll
            for (int mt = 0; mt < MT; ++mt)
#pragma unroll
                for (int nt = 0; nt < NT; ++nt)
                    MMA_BF16(acc[mt][nt], aH[mt], bH[nt]);
#pragma unroll
            for (int mt = 0; mt < MT; ++mt)
#pragma unroll
                for (int nt = 0; nt < NT; ++nt)
                    MMA_BF16(acc[mt][nt], aL[mt], bH[nt]);
#pragma unroll
            for (int mt = 0; mt < MT; ++mt)
#pragma unroll
                for (int nt = 0; nt < NT; ++nt)
                    MMA_BF16(acc[mt][nt], aH[mt], bL[nt]);
        }
        __syncthreads();
    }

    // Epilogue
    const int rbase = bm + wm + (lane >> 2);
    const int cbase = bn + wn + 2 * (lane & 3);
#pragma unroll
    for (int mt = 0; mt < MT; ++mt) {
        const int R0 = rbase + mt * 16;
        const int R1 = R0 + 8;
        const int t0 = R0 & (T - 1);
        const int t1 = R1 & (T - 1);
#pragma unroll
        for (int nt = 0; nt < NT; ++nt) {
            const int C = cbase + nt * 8;
            float2 v01, v23;
            v01.x = acc[mt][nt][0];
            v01.y = acc[mt][nt][1];
            v23.x = acc[mt][nt][2];
            v23.y = acc[mt][nt][3];
            if (SCALED) {
                const float s0 = g_S[(size_t)C * T + t0];
                const float s1 = g_S[(size_t)(C + 1) * T + t0];
                const float s2 = g_S[(size_t)C * T + t1];
                const float s3 = g_S[(size_t)(C + 1) * T + t1];
                v01.x *= s0; v01.y *= s1;
                v23.x *= s2; v23.y *= s3;
            }
            *reinterpret_cast<float2*>(&Cout[(size_t)R0 * D + C]) = v01;
            *reinterpret_cast<float2*>(&Cout[(size_t)R1 * D + C]) = v23;
        }
    }
}

constexpr int SMEM_BIG   = 3 * 2 * (128 * 64 + 128 * 64);  // 98304
constexpr int SMEM_SMALL = 3 * 2 * (64 * 64 + 64 * 64);    // 49152

// ---------------------------------------------------------------------------
extern "C" void kernel_launch(void* const* d_in, const int* in_sizes, int n_in,
                              void* d_out, int out_size) {
    const float* x  = (const float*)d_in[0];
    const float* Wq = (const float*)d_in[1];
    const float* Wk = (const float*)d_in[2];
    const float* Wv = (const float*)d_in[3];
    float* out = (float*)d_out;

    cudaFuncSetAttribute(mma_gemm<false, 2, 2>,
                         cudaFuncAttributeMaxDynamicSharedMemorySize, SMEM_SMALL);
    cudaFuncSetAttribute(mma_gemm<true, 4, 4>,
                         cudaFuncAttributeMaxDynamicSharedMemorySize, SMEM_BIG);

    // A: row-sums of Wv (coalesced)
    wvsum_kernel<<<8, 256>>>(Wv);
    // W: split+transpose Wq/Wk into bf16 hi/lo
    wconv_kernel<<<dim3(2, 8), 256>>>(Wq, Wk);
    // B: vsum fold + y (also emits x hi/lo split)
    y_kernel<<<T, 256>>>(x);
    // C: c = y @ Wk via warp-MMA, 64x64 tiles (128 CTAs)
    mma_gemm<false, 2, 2><<<dim3(T / 64, D / 64), 256, SMEM_SMALL>>>(nullptr);
    // D: blocked decay scan -> S
    scan_local_kernel<<<SCAN_P, 256>>>();
    scan_carry_kernel<<<1, 256>>>();
    scan_combine_kernel<<<SCAN_P, 256>>>();
    // E: out = S2 .* (x @ Wq) via warp-MMA, 128x128 tiles
    mma_gemm<true, 4, 4><<<dim3(MBIG / 128, D / 128), 256, SMEM_BIG>>>(out);
}

// round 13
// speedup vs baseline: 8.6041x; 1.0086x over previous
#include <cuda_runtime.h>
#include <cuda_bf16.h>
#include <cstdint>

// Problem constants
constexpr int B = 16;
constexpr int T = 2048;
constexpr int D = 256;
constexpr int MBIG = B * T;          // 32768
constexpr int SCAN_L = 32;
constexpr int SCAN_P = T / SCAN_L;   // 64
constexpr float GAMMA   = 0.9f;
constexpr float GAMMA32 = 0.03433683820292512f;  // 0.9^32

// ---------------------------------------------------------------------------
// Static device scratch
// ---------------------------------------------------------------------------
__device__ __align__(16) __nv_bfloat16 g_xhi[MBIG * D];
__device__ __align__(16) __nv_bfloat16 g_xlo[MBIG * D];
__device__ __align__(16) __nv_bfloat16 g_yhi[T * D];
__device__ __align__(16) __nv_bfloat16 g_ylo[T * D];
__device__ __align__(16) __nv_bfloat16 g_wqt_hi[D * D];  // transposed: [n][k]
__device__ __align__(16) __nv_bfloat16 g_wqt_lo[D * D];
__device__ __align__(16) __nv_bfloat16 g_wkt_hi[D * D];
__device__ __align__(16) __nv_bfloat16 g_wkt_lo[D * D];
__device__ float g_wvsum[D];
__device__ float g_c[T * D];
__device__ float g_S[T * D];
__device__ float g_carry[SCAN_P * D];
__device__ float g_pre[SCAN_P * D];

// ---------------------------------------------------------------------------
// Helpers (baseline PTX only)
// ---------------------------------------------------------------------------
__device__ __forceinline__ uint32_t smem_u32(const void* p) {
    uint32_t a;
    asm("{ .reg .u64 t; cvta.to.shared.u64 t, %1; cvt.u32.u64 %0, t; }"
        : "=r"(a) : "l"(p));
    return a;
}

__device__ __forceinline__ void cp16(uint32_t s, const void* g) {
    asm volatile("cp.async.cg.shared.global [%0], [%1], 16;"
                 :: "r"(s), "l"(g) : "memory");
}
__device__ __forceinline__ void cp_commit() {
    asm volatile("cp.async.commit_group;" ::: "memory");
}
template <int N>
__device__ __forceinline__ void cp_wait() {
    asm volatile("cp.async.wait_group %0;" :: "n"(N) : "memory");
}

#define LDSM_X4(r0, r1, r2, r3, addr) \
    asm volatile("ldmatrix.sync.aligned.m8n8.x4.shared.b16 {%0,%1,%2,%3}, [%4];" \
                 : "=r"(r0), "=r"(r1), "=r"(r2), "=r"(r3) : "r"(addr))

#define MMA_BF16(c, a, b) \
    asm volatile("mma.sync.aligned.m16n8k16.row.col.f32.bf16.bf16.f32 " \
                 "{%0,%1,%2,%3}, {%4,%5,%6,%7}, {%8,%9}, {%0,%1,%2,%3};" \
                 : "+f"((c)[0]), "+f"((c)[1]), "+f"((c)[2]), "+f"((c)[3]) \
                 : "r"((a)[0]), "r"((a)[1]), "r"((a)[2]), "r"((a)[3]), \
                   "r"((b)[0]), "r"((b)[1]))

// ---------------------------------------------------------------------------
// Kernel A: wv_sum[i] = sum_j Wv[i][j]   (grid 8 x 256, coalesced)
// ---------------------------------------------------------------------------
__global__ void wvsum_kernel(const float* __restrict__ Wv) {
    const int warp = threadIdx.x >> 5, lane = threadIdx.x & 31;
    const int row0 = blockIdx.x * 32 + warp * 4;
#pragma unroll
    for (int rr = 0; rr < 4; ++rr) {
        const int row = row0 + rr;
        float s = 0.f;
#pragma unroll
        for (int i = 0; i < 8; ++i)
            s += Wv[row * D + lane + 32 * i];
#pragma unroll
        for (int o = 16; o > 0; o >>= 1)
            s += __shfl_xor_sync(0xffffffffu, s, o);
        if (lane == 0) g_wvsum[row] = s;
    }
}

// ---------------------------------------------------------------------------
// Kernel W: split + transpose Wq and Wk into bf16 hi/lo, [n][k] layout.
// ---------------------------------------------------------------------------
__global__ void wconv_kernel(const float* __restrict__ Wq,
                             const float* __restrict__ Wk) {
    const float* W = blockIdx.x ? Wk : Wq;
    __nv_bfloat16* hi = blockIdx.x ? g_wkt_hi : g_wqt_hi;
    __nv_bfloat16* lo = blockIdx.x ? g_wkt_lo : g_wqt_lo;
    const int n  = blockIdx.y * 32 + (threadIdx.x & 31);
    const int k0 = (threadIdx.x >> 5) * 32;
#pragma unroll 4
    for (int kk = 0; kk < 32; ++kk) {
        const int k = k0 + kk;
        float v = W[k * D + n];
        __nv_bfloat16 h = __float2bfloat16_rn(v);
        hi[n * D + k] = h;
        lo[n * D + k] = __float2bfloat16_rn(v - __bfloat162float(h));
    }
}

// ---------------------------------------------------------------------------
// Kernel B: per-t fold over batch + x/y bf16 hi/lo splits.
// Splits staged in SMEM, written with 16B vector stores (8x fewer STGs).
// ---------------------------------------------------------------------------
__global__ void y_kernel(const float* __restrict__ x) {
    const int t = blockIdx.x;
    const int d = threadIdx.x;
    __shared__ float xs[B][D];
    __shared__ float wvs[D];
    __shared__ float vs[B];
    __shared__ __nv_bfloat16 hs[B][D];
    __shared__ __nv_bfloat16 ls[B][D];

    wvs[d] = g_wvsum[d];
#pragma unroll
    for (int b = 0; b < B; ++b)
        xs[b][d] = x[((size_t)b * T + t) * D + d];
    __syncthreads();

    // split into smem staging
#pragma unroll
    for (int b = 0; b < B; ++b) {
        float v = xs[b][d];
        __nv_bfloat16 h = __float2bfloat16_rn(v);
        hs[b][d] = h;
        ls[b][d] = __float2bfloat16_rn(v - __bfloat162float(h));
    }

    const int warp = d >> 5, lane = d & 31;
#pragma unroll
    for (int bb = 0; bb < 2; ++bb) {
        const int b = warp * 2 + bb;
        float p = 0.f;
#pragma unroll
        for (int i = 0; i < D / 32; ++i)
            p += xs[b][lane + 32 * i] * wvs[lane + 32 * i];
#pragma unroll
        for (int o = 16; o > 0; o >>= 1)
            p += __shfl_xor_sync(0xffffffffu, p, o);
        if (lane == 0) vs[b] = p;
    }
    __syncthreads();

    float acc = 0.f;
#pragma unroll
    for (int b = 0; b < B; ++b)
        acc += vs[b] * xs[b][d];
    __nv_bfloat16 h = __float2bfloat16_rn(acc);
    g_yhi[t * D + d] = h;
    g_ylo[t * D + d] = __float2bfloat16_rn(acc - __bfloat162float(h));

    // vector-store split x: 512 uint4 per array, 256 threads -> 2 iters
    const uint4* hv = reinterpret_cast<const uint4*>(&hs[0][0]);
    const uint4* lv = reinterpret_cast<const uint4*>(&ls[0][0]);
#pragma unroll
    for (int it = 0; it < 2; ++it) {
        const int idx = d + it * 256;        // 0..511
        const int b = idx >> 5;              // 32 uint4 per row
        const int ch = idx & 31;
        const size_t o = (((size_t)b * T + t) * D + ch * 8) / 8;
        reinterpret_cast<uint4*>(g_xhi)[o] = hv[idx];
        reinterpret_cast<uint4*>(g_xlo)[o] = lv[idx];
    }
}

// ---------------------------------------------------------------------------
// Blocked decay scan
// ---------------------------------------------------------------------------
__global__ __launch_bounds__(256) void scan_local_kernel() {
    const int p = blockIdx.x, d = threadIdx.x;
    float v[SCAN_L];
#pragma unroll
    for (int i = 0; i < SCAN_L; ++i) {
        const int t = p * SCAN_L + i;
        v[i] = (t == 0) ? 0.f : g_c[t * D + d];
    }
    float r = 0.f;
#pragma unroll
    for (int i = 0; i < SCAN_L; ++i) {
        r = GAMMA * r + v[i];
        v[i] = r;
    }
#pragma unroll
    for (int i = 0; i < SCAN_L; ++i)
        g_S[(p * SCAN_L + i) * D + d] = v[i];
    g_carry[p * D + d] = r;
}

__global__ __launch_bounds__(256) void scan_carry_kernel() {
    const int d = threadIdx.x;
    float c[SCAN_P];
#pragma unroll
    for (int p = 0; p < SCAN_P; ++p)
        c[p] = g_carry[p * D + d];
    float r = 0.f;
#pragma unroll
    for (int p = 0; p < SCAN_P; ++p) {
        g_pre[p * D + d] = r;
        r = c[p] + GAMMA32 * r;
    }
}

__global__ __launch_bounds__(256) void scan_combine_kernel() {
    const int p = blockIdx.x, d = threadIdx.x;
    const float pre = g_pre[p * D + d];
    float v[SCAN_L];
#pragma unroll
    for (int i = 0; i < SCAN_L; ++i)
        v[i] = g_S[(p * SCAN_L + i) * D + d];
    float gp = GAMMA;
#pragma unroll
    for (int i = 0; i < SCAN_L; ++i) {
        v[i] += gp * pre;
        gp *= GAMMA;
    }
#pragma unroll
    for (int i = 0; i < SCAN_L; ++i)
        g_S[(p * SCAN_L + i) * D + d] = v[i];
    if (p == 0)
        g_S[d] = v[1];   // S[0] := r[1]
}

// ---------------------------------------------------------------------------
// Warp-MMA GEMM (legacy HMMA path), templated on fragment counts:
//   warp grid fixed 2x4; BM = 32*MT, BN = 32*NT; BK=32; 3-stage cp.async.
// Per-ks fragment hoist: hi/lo fragments ldmatrix'd once, 3 terms from regs.
// 16B-chunk XOR swizzle: chunk' = chunk ^ ((row>>1)&3)  (conflict-free LDSM).
// launch_bounds(256,3): target 3 CTAs/SM for latency hiding.
// ---------------------------------------------------------------------------
template <bool SCALED, int MT, int NT>
__global__ __launch_bounds__(256, 3)
void mma_gemm(float* __restrict__ Cout_arg) {
    constexpr int BM = 32 * MT;
    constexpr int BN = 32 * NT;
    constexpr int ASZ = BM * 64;           // one A tile (BMx32 bf16), bytes
    constexpr int BSZ = BN * 64;
    constexpr int STAGE = 2 * (ASZ + BSZ); // Ahi, Alo, Bhi, Blo

    extern __shared__ char smem[];
    const uint32_t smem_u = smem_u32(smem);

    const int tid  = threadIdx.x;
    const int wid  = tid >> 5;
    const int lane = tid & 31;
    const int wm = (wid >> 2) * (MT * 16);   // warp M offset
    const int wn = (wid & 3) * (NT * 8);     // warp N offset

    const int bm = blockIdx.x * BM;
    const int bn = blockIdx.y * BN;

    const __nv_bfloat16* const Ahi = (SCALED ? g_xhi : g_yhi) + (size_t)bm * D;
    const __nv_bfloat16* const Alo = (SCALED ? g_xlo : g_ylo) + (size_t)bm * D;
    const __nv_bfloat16* const Bhi = (SCALED ? g_wqt_hi : g_wkt_hi) + (size_t)bn * D;
    const __nv_bfloat16* const Blo = (SCALED ? g_wqt_lo : g_wkt_lo) + (size_t)bn * D;
    float* const Cout = SCALED ? Cout_arg : g_c;

    auto load_stage = [&](int stg, int chunk) {
        const int kc = chunk * 32;
        const uint32_t sb = smem_u + stg * STAGE;
#pragma unroll
        for (int t4 = 0; t4 < 2; ++t4) {          // A hi, A lo
            const uint32_t tb = sb + t4 * ASZ;
            const __nv_bfloat16* src = t4 ? Alo : Ahi;
#pragma unroll
            for (int idx = 0; idx < BM * 4 / 256; ++idx) {
                const int q = tid + idx * 256;
                const int r = q >> 2, ch = q & 3;
                const uint32_t s = tb + r * 64 + ((ch ^ ((r >> 1) & 3)) << 4);
                cp16(s, src + (size_t)r * D + kc + ch * 8);
            }
        }
#pragma unroll
        for (int t4 = 0; t4 < 2; ++t4) {          // B hi, B lo
            const uint32_t tb = sb + 2 * ASZ + t4 * BSZ;
            const __nv_bfloat16* src = t4 ? Blo : Bhi;
#pragma unroll
            for (int idx = 0; idx < BN * 4 / 256; ++idx) {
                const int q = tid + idx * 256;
                const int r = q >> 2, ch = q & 3;
                const uint32_t s = tb + r * 64 + ((ch ^ ((r >> 1) & 3)) << 4);
                cp16(s, src + (size_t)r * D + kc + ch * 8);
            }
        }
    };

    // per-lane ldmatrix row/koct components
    const int laneA_r = ((lane & 8) ? 8 : 0) + (lane & 7);
    const int laneA_k = (lane & 16) ? 1 : 0;
    const int mi = lane >> 3;
    const int laneB_ns = mi >> 1;
    const int laneB_k  = mi & 1;
    const int laneB_r  = lane & 7;

    float acc[MT][NT][4];
#pragma unroll
    for (int a = 0; a < MT; ++a)
#pragma unroll
        for (int b = 0; b < NT; ++b)
#pragma unroll
            for (int q = 0; q < 4; ++q) acc[a][b][q] = 0.f;

    load_stage(0, 0);
    cp_commit();
    load_stage(1, 1);
    cp_commit();

#pragma unroll 1
    for (int chunk = 0; chunk < 8; ++chunk) {
        const int stg = chunk % 3;
        if (chunk + 2 < 8) {
            load_stage((chunk + 2) % 3, chunk + 2);
            cp_commit();
            cp_wait<2>();
        } else if (chunk + 1 < 8) {
            cp_wait<1>();
        } else {
            cp_wait<0>();
        }
        __syncthreads();

        const uint32_t sb = smem_u + stg * STAGE;
#pragma unroll
        for (int ks = 0; ks < 32; ks += 16) {
            const int ko = (ks >> 3);
            // --- hoist all fragments for this ks ---
            uint32_t aH[MT][4], aL[MT][4], bH[NT][2], bL[NT][2];
#pragma unroll
            for (int mt = 0; mt < MT; ++mt) {
                const int R = wm + mt * 16 + laneA_r;
                const int kk = ko + laneA_k;
                const uint32_t sw = R * 64 + ((kk ^ ((R >> 1) & 3)) << 4);
                LDSM_X4(aH[mt][0], aH[mt][1], aH[mt][2], aH[mt][3], sb + sw);
                LDSM_X4(aL[mt][0], aL[mt][1], aL[mt][2], aL[mt][3],
                        sb + ASZ + sw);
            }
#pragma unroll
            for (int g = 0; g < NT / 2; ++g) {
                const int R = wn + (2 * g + laneB_ns) * 8 + laneB_r;
                const int kk = ko + laneB_k;
                const uint32_t sw = R * 64 + ((kk ^ ((R >> 1) & 3)) << 4);
                LDSM_X4(bH[2 * g][0], bH[2 * g][1],
                        bH[2 * g + 1][0], bH[2 * g + 1][1], sb + 2 * ASZ + sw);
                LDSM_X4(bL[2 * g][0], bL[2 * g][1],
                        bL[2 * g + 1][0], bL[2 * g + 1][1],
                        sb + 2 * ASZ + BSZ + sw);
            }
            // --- 3 split terms from registers ---
#pragma unroll
            for (int mt = 0; mt < MT; ++mt)
#pragma unroll
                for (int nt = 0; nt < NT; ++nt)
                    MMA_BF16(acc[mt][nt], aH[mt], bH[nt]);
#pragma unroll
            for (int mt = 0; mt < MT; ++mt)
#pragma unroll
                for (int nt = 0; nt < NT; ++nt)
                    MMA_BF16(acc[mt][nt], aL[mt], bH[nt]);
#pragma unroll
            for (int mt = 0; mt < MT; ++mt)
#pragma unroll
                for (int nt = 0; nt < NT; ++nt)
                    MMA_BF16(acc[mt][nt], aH[mt], bL[nt]);
        }
        __syncthreads();
    }

    // Epilogue
    const int rbase = bm + wm + (lane >> 2);
    const int cbase = bn + wn + 2 * (lane & 3);
#pragma unroll
    for (int mt = 0; mt < MT; ++mt) {
        const int R0 = rbase + mt * 16;
        const int R1 = R0 + 8;
        const int t0 = R0 & (T - 1);
        const int t1 = R1 & (T - 1);
#pragma unroll
        for (int nt = 0; nt < NT; ++nt) {
            const int C = cbase + nt * 8;
            float2 v01, v23;
            v01.x = acc[mt][nt][0];
            v01.y = acc[mt][nt][1];
            v23.x = acc[mt][nt][2];
            v23.y = acc[mt][nt][3];
            if (SCALED) {
                const float s0 = g_S[(size_t)C * T + t0];
                const float s1 = g_S[(size_t)(C + 1) * T + t0];
                const float s2 = g_S[(size_t)C * T + t1];
                const float s3 = g_S[(size_t)(C + 1) * T + t1];
                v01.x *= s0; v01.y *= s1;
                v23.x *= s2; v23.y *= s3;
            }
            *reinterpret_cast<float2*>(&Cout[(size_t)R0 * D + C]) = v01;
            *reinterpret_cast<float2*>(&Cout[(size_t)R1 * D + C]) = v23;
        }
    }
}

constexpr int SMEM_BIG   = 3 * 2 * (64 * 64 + 128 * 64);   // 73728
constexpr int SMEM_SMALL = 3 * 2 * (64 * 64 + 64 * 64);    // 49152

// ---------------------------------------------------------------------------
extern "C" void kernel_launch(void* const* d_in, const int* in_sizes, int n_in,
                              void* d_out, int out_size) {
    const float* x  = (const float*)d_in[0];
    const float* Wq = (const float*)d_in[1];
    const float* Wk = (const float*)d_in[2];
    const float* Wv = (const float*)d_in[3];
    float* out = (float*)d_out;

    cudaFuncSetAttribute(mma_gemm<false, 2, 2>,
                         cudaFuncAttributeMaxDynamicSharedMemorySize, SMEM_SMALL);
    cudaFuncSetAttribute(mma_gemm<true, 2, 4>,
                         cudaFuncAttributeMaxDynamicSharedMemorySize, SMEM_BIG);

    // A: row-sums of Wv (coalesced)
    wvsum_kernel<<<8, 256>>>(Wv);
    // W: split+transpose Wq/Wk into bf16 hi/lo
    wconv_kernel<<<dim3(2, 8), 256>>>(Wq, Wk);
    // B: vsum fold + y (vectorized split stores)
    y_kernel<<<T, 256>>>(x);
    // C: c = y @ Wk via warp-MMA, 64x64 tiles (128 CTAs)
    mma_gemm<false, 2, 2><<<dim3(T / 64, D / 64), 256, SMEM_SMALL>>>(nullptr);
    // D: blocked decay scan -> S
    scan_local_kernel<<<SCAN_P, 256>>>();
    scan_carry_kernel<<<1, 256>>>();
    scan_combine_kernel<<<SCAN_P, 256>>>();
    // E: out = S2 .* (x @ Wq) via warp-MMA, 64x128 tiles, 3 CTAs/SM
    mma_gemm<true, 2, 4><<<dim3(MBIG / 64, D / 128), 256, SMEM_BIG>>>(out);
}

// round 15
// speedup vs baseline: 9.0331x; 1.0499x over previous
#include <cuda_runtime.h>
#include <cuda_bf16.h>
#include <cstdint>

// Problem constants
constexpr int B = 16;
constexpr int T = 2048;
constexpr int D = 256;
constexpr int MBIG = B * T;          // 32768
constexpr int SCAN_L = 32;
constexpr int SCAN_P = T / SCAN_L;   // 64
constexpr float GAMMA   = 0.9f;
constexpr float GAMMA32 = 0.03433683820292512f;  // 0.9^32

// ---------------------------------------------------------------------------
// Static device scratch
// ---------------------------------------------------------------------------
__device__ __align__(16) __nv_bfloat16 g_yhi[T * D];
__device__ __align__(16) __nv_bfloat16 g_ylo[T * D];
__device__ __align__(16) __nv_bfloat16 g_wqt_hi[D * D];  // transposed: [n][k]
__device__ __align__(16) __nv_bfloat16 g_wqt_lo[D * D];
__device__ __align__(16) __nv_bfloat16 g_wkt_hi[D * D];
__device__ __align__(16) __nv_bfloat16 g_wkt_lo[D * D];
__device__ float g_wvsum[D];
__device__ float g_c[T * D];
__device__ float g_S[T * D];
__device__ float g_carry[SCAN_P * D];
__device__ float g_pre[SCAN_P * D];

// ---------------------------------------------------------------------------
// Helpers (baseline PTX only)
// ---------------------------------------------------------------------------
__device__ __forceinline__ uint32_t smem_u32(const void* p) {
    uint32_t a;
    asm("{ .reg .u64 t; cvta.to.shared.u64 t, %1; cvt.u32.u64 %0, t; }"
        : "=r"(a) : "l"(p));
    return a;
}

__device__ __forceinline__ void cp16(uint32_t s, const void* g) {
    asm volatile("cp.async.cg.shared.global [%0], [%1], 16;"
                 :: "r"(s), "l"(g) : "memory");
}
__device__ __forceinline__ void cp_commit() {
    asm volatile("cp.async.commit_group;" ::: "memory");
}
template <int N>
__device__ __forceinline__ void cp_wait() {
    asm volatile("cp.async.wait_group %0;" :: "n"(N) : "memory");
}

#define LDSM_X4(r0, r1, r2, r3, addr) \
    asm volatile("ldmatrix.sync.aligned.m8n8.x4.shared.b16 {%0,%1,%2,%3}, [%4];" \
                 : "=r"(r0), "=r"(r1), "=r"(r2), "=r"(r3) : "r"(addr))

#define MMA_BF16(c, a, b) \
    asm volatile("mma.sync.aligned.m16n8k16.row.col.f32.bf16.bf16.f32 " \
                 "{%0,%1,%2,%3}, {%4,%5,%6,%7}, {%8,%9}, {%0,%1,%2,%3};" \
                 : "+f"((c)[0]), "+f"((c)[1]), "+f"((c)[2]), "+f"((c)[3]) \
                 : "r"((a)[0]), "r"((a)[1]), "r"((a)[2]), "r"((a)[3]), \
                   "r"((b)[0]), "r"((b)[1]))

// ---------------------------------------------------------------------------
// Kernel A: wv_sum[i] = sum_j Wv[i][j]   (grid 8 x 256, coalesced)
// ---------------------------------------------------------------------------
__global__ void wvsum_kernel(const float* __restrict__ Wv) {
    const int warp = threadIdx.x >> 5, lane = threadIdx.x & 31;
    const int row0 = blockIdx.x * 32 + warp * 4;
#pragma unroll
    for (int rr = 0; rr < 4; ++rr) {
        const int row = row0 + rr;
        float s = 0.f;
#pragma unroll
        for (int i = 0; i < 8; ++i)
            s += Wv[row * D + lane + 32 * i];
#pragma unroll
        for (int o = 16; o > 0; o >>= 1)
            s += __shfl_xor_sync(0xffffffffu, s, o);
        if (lane == 0) g_wvsum[row] = s;
    }
}

// ---------------------------------------------------------------------------
// Kernel W: split + transpose Wq and Wk into bf16 hi/lo, [n][k] layout.
// ---------------------------------------------------------------------------
__global__ void wconv_kernel(const float* __restrict__ Wq,
                             const float* __restrict__ Wk) {
    const float* W = blockIdx.x ? Wk : Wq;
    __nv_bfloat16* hi = blockIdx.x ? g_wkt_hi : g_wqt_hi;
    __nv_bfloat16* lo = blockIdx.x ? g_wkt_lo : g_wqt_lo;
    const int n  = blockIdx.y * 32 + (threadIdx.x & 31);
    const int k0 = (threadIdx.x >> 5) * 32;
#pragma unroll 4
    for (int kk = 0; kk < 32; ++kk) {
        const int k = k0 + kk;
        float v = W[k * D + n];
        __nv_bfloat16 h = __float2bfloat16_rn(v);
        hi[n * D + k] = h;
        lo[n * D + k] = __float2bfloat16_rn(v - __bfloat162float(h));
    }
}

// ---------------------------------------------------------------------------
// Kernel B: per-t fold over batch (lean: y hi/lo split only).
// ---------------------------------------------------------------------------
__global__ void y_kernel(const float* __restrict__ x) {
    const int t = blockIdx.x;
    const int d = threadIdx.x;
    __shared__ float xs[B][D];
    __shared__ float wvs[D];
    __shared__ float vs[B];

    wvs[d] = g_wvsum[d];
#pragma unroll
    for (int b = 0; b < B; ++b)
        xs[b][d] = x[((size_t)b * T + t) * D + d];
    __syncthreads();

    const int warp = d >> 5, lane = d & 31;
#pragma unroll
    for (int bb = 0; bb < 2; ++bb) {
        const int b = warp * 2 + bb;
        float p = 0.f;
#pragma unroll
        for (int i = 0; i < D / 32; ++i)
            p += xs[b][lane + 32 * i] * wvs[lane + 32 * i];
#pragma unroll
        for (int o = 16; o > 0; o >>= 1)
            p += __shfl_xor_sync(0xffffffffu, p, o);
        if (lane == 0) vs[b] = p;
    }
    __syncthreads();

    float acc = 0.f;
#pragma unroll
    for (int b = 0; b < B; ++b)
        acc += vs[b] * xs[b][d];
    __nv_bfloat16 h = __float2bfloat16_rn(acc);
    g_yhi[t * D + d] = h;
    g_ylo[t * D + d] = __float2bfloat16_rn(acc - __bfloat162float(h));
}

// ---------------------------------------------------------------------------
// Blocked decay scan
// ---------------------------------------------------------------------------
__global__ __launch_bounds__(256) void scan_local_kernel() {
    const int p = blockIdx.x, d = threadIdx.x;
    float v[SCAN_L];
#pragma unroll
    for (int i = 0; i < SCAN_L; ++i) {
        const int t = p * SCAN_L + i;
        v[i] = (t == 0) ? 0.f : g_c[t * D + d];
    }
    float r = 0.f;
#pragma unroll
    for (int i = 0; i < SCAN_L; ++i) {
        r = GAMMA * r + v[i];
        v[i] = r;
    }
#pragma unroll
    for (int i = 0; i < SCAN_L; ++i)
        g_S[(p * SCAN_L + i) * D + d] = v[i];
    g_carry[p * D + d] = r;
}

__global__ __launch_bounds__(256) void scan_carry_kernel() {
    const int d = threadIdx.x;
    float c[SCAN_P];
#pragma unroll
    for (int p = 0; p < SCAN_P; ++p)
        c[p] = g_carry[p * D + d];
    float r = 0.f;
#pragma unroll
    for (int p = 0; p < SCAN_P; ++p) {
        g_pre[p * D + d] = r;
        r = c[p] + GAMMA32 * r;
    }
}

__global__ __launch_bounds__(256) void scan_combine_kernel() {
    const int p = blockIdx.x, d = threadIdx.x;
    const float pre = g_pre[p * D + d];
    float v[SCAN_L];
#pragma unroll
    for (int i = 0; i < SCAN_L; ++i)
        v[i] = g_S[(p * SCAN_L + i) * D + d];
    float gp = GAMMA;
#pragma unroll
    for (int i = 0; i < SCAN_L; ++i) {
        v[i] += gp * pre;
        gp *= GAMMA;
    }
#pragma unroll
    for (int i = 0; i < SCAN_L; ++i)
        g_S[(p * SCAN_L + i) * D + d] = v[i];
    if (p == 0)
        g_S[d] = v[1];   // S[0] := r[1]
}

// ---------------------------------------------------------------------------
// Small GEMM: c = y @ Wk^T  (64x64 tiles, split inputs pre-materialized)
// Warp grid 2x4, MT=NT=2, BK=32, 3-stage cp.async, fragment hoist.
// ---------------------------------------------------------------------------
constexpr int SMEM_SMALL = 3 * 2 * (64 * 64 + 64 * 64);    // 49152

__global__ __launch_bounds__(256, 3)
void yk_gemm() {
    constexpr int MT = 2, NT = 2;
    constexpr int BM = 64, BN = 64;
    constexpr int ASZ = BM * 64;
    constexpr int BSZ = BN * 64;
    constexpr int STAGE = 2 * (ASZ + BSZ);

    extern __shared__ char smem[];
    const uint32_t smem_u = smem_u32(smem);

    const int tid  = threadIdx.x;
    const int wid  = tid >> 5;
    const int lane = tid & 31;
    const int wm = (wid >> 2) * (MT * 16);
    const int wn = (wid & 3) * (NT * 8);

    const int bm = blockIdx.x * BM;
    const int bn = blockIdx.y * BN;

    const __nv_bfloat16* const Ahi = g_yhi + (size_t)bm * D;
    const __nv_bfloat16* const Alo = g_ylo + (size_t)bm * D;
    const __nv_bfloat16* const Bhi = g_wkt_hi + (size_t)bn * D;
    const __nv_bfloat16* const Blo = g_wkt_lo + (size_t)bn * D;

    auto load_stage = [&](int stg, int chunk) {
        const int kc = chunk * 32;
        const uint32_t sb = smem_u + stg * STAGE;
        const __nv_bfloat16* srcs[4] = { Ahi, Alo, Bhi, Blo };
#pragma unroll
        for (int t4 = 0; t4 < 4; ++t4) {
            const uint32_t tb = sb + t4 * ASZ;
            const int q = tid;
            const int r = q >> 2, ch = q & 3;
            const uint32_t s = tb + r * 64 + ((ch ^ ((r >> 1) & 3)) << 4);
            cp16(s, srcs[t4] + (size_t)r * D + kc + ch * 8);
        }
    };

    const int laneA_r = ((lane & 8) ? 8 : 0) + (lane & 7);
    const int laneA_k = (lane & 16) ? 1 : 0;
    const int mi = lane >> 3;
    const int laneB_ns = mi >> 1;
    const int laneB_k  = mi & 1;
    const int laneB_r  = lane & 7;

    float acc[MT][NT][4];
#pragma unroll
    for (int a = 0; a < MT; ++a)
#pragma unroll
        for (int b = 0; b < NT; ++b)
#pragma unroll
            for (int q = 0; q < 4; ++q) acc[a][b][q] = 0.f;

    load_stage(0, 0);
    cp_commit();
    load_stage(1, 1);
    cp_commit();

#pragma unroll 1
    for (int chunk = 0; chunk < 8; ++chunk) {
        const int stg = chunk % 3;
        if (chunk + 2 < 8) {
            load_stage((chunk + 2) % 3, chunk + 2);
            cp_commit();
            cp_wait<2>();
        } else if (chunk + 1 < 8) {
            cp_wait<1>();
        } else {
            cp_wait<0>();
        }
        __syncthreads();

        const uint32_t sb = smem_u + stg * STAGE;
#pragma unroll
        for (int ks = 0; ks < 32; ks += 16) {
            const int ko = (ks >> 3);
            uint32_t aH[MT][4], aL[MT][4], bH[NT][2], bL[NT][2];
#pragma unroll
            for (int mt = 0; mt < MT; ++mt) {
                const int R = wm + mt * 16 + laneA_r;
                const int kk = ko + laneA_k;
                const uint32_t sw = R * 64 + ((kk ^ ((R >> 1) & 3)) << 4);
                LDSM_X4(aH[mt][0], aH[mt][1], aH[mt][2], aH[mt][3], sb + sw);
                LDSM_X4(aL[mt][0], aL[mt][1], aL[mt][2], aL[mt][3],
                        sb + ASZ + sw);
            }
#pragma unroll
            for (int g = 0; g < NT / 2; ++g) {
                const int R = wn + (2 * g + laneB_ns) * 8 + laneB_r;
                const int kk = ko + laneB_k;
                const uint32_t sw = R * 64 + ((kk ^ ((R >> 1) & 3)) << 4);
                LDSM_X4(bH[2 * g][0], bH[2 * g][1],
                        bH[2 * g + 1][0], bH[2 * g + 1][1], sb + 2 * ASZ + sw);
                LDSM_X4(bL[2 * g][0], bL[2 * g][1],
                        bL[2 * g + 1][0], bL[2 * g + 1][1],
                        sb + 2 * ASZ + BSZ + sw);
            }
#pragma unroll
            for (int mt = 0; mt < MT; ++mt)
#pragma unroll
                for (int nt = 0; nt < NT; ++nt)
                    MMA_BF16(acc[mt][nt], aH[mt], bH[nt]);
#pragma unroll
            for (int mt = 0; mt < MT; ++mt)
#pragma unroll
                for (int nt = 0; nt < NT; ++nt)
                    MMA_BF16(acc[mt][nt], aL[mt], bH[nt]);
#pragma unroll
            for (int mt = 0; mt < MT; ++mt)
#pragma unroll
                for (int nt = 0; nt < NT; ++nt)
                    MMA_BF16(acc[mt][nt], aH[mt], bL[nt]);
        }
        __syncthreads();
    }

    const int rbase = bm + wm + (lane >> 2);
    const int cbase = bn + wn + 2 * (lane & 3);
#pragma unroll
    for (int mt = 0; mt < MT; ++mt) {
        const int R0 = rbase + mt * 16;
#pragma unroll
        for (int nt = 0; nt < NT; ++nt) {
            const int C = cbase + nt * 8;
            float2 v01, v23;
            v01.x = acc[mt][nt][0];
            v01.y = acc[mt][nt][1];
            v23.x = acc[mt][nt][2];
            v23.y = acc[mt][nt][3];
            *reinterpret_cast<float2*>(&g_c[(size_t)R0 * D + C]) = v01;
            *reinterpret_cast<float2*>(&g_c[(size_t)(R0 + 8) * D + C]) = v23;
        }
    }
}

// ---------------------------------------------------------------------------
// Big GEMM, fused x-split: out[m, 0:256] = S2 .* (x @ Wq)
// BM=64, full N=256 per CTA (x read ONCE as fp32, hi/lo computed in-kernel).
// 8 warps 2x4; warp tile 32 x 64 (N in 2 halves of 4 frags). 2-stage pipeline.
// Stage: Af32 8KB | Ahi 4KB | Alo 4KB | Bhi 16KB | Blo 16KB = 48KB. x2 = 96KB.
// ---------------------------------------------------------------------------
constexpr int XQ_STAGE = 49152;
constexpr int SMEM_BIG = 2 * XQ_STAGE;   // 98304

__global__ __launch_bounds__(256, 2)
void xq_gemm(const float* __restrict__ x, float* __restrict__ out) {
    constexpr int AF32 = 0;         // 64 rows x 128B
    constexpr int AHI  = 8192;      // 64 rows x 64B, swizzled
    constexpr int ALO  = 12288;
    constexpr int BHI  = 16384;     // 256 rows x 64B, swizzled
    constexpr int BLO  = 32768;

    extern __shared__ char smem[];
    const uint32_t smem_u = smem_u32(smem);

    const int tid  = threadIdx.x;
    const int wid  = tid >> 5;
    const int lane = tid & 31;
    const int wm = (wid >> 2) * 32;     // warp M offset (2 groups of 32)
    const int wn = (wid & 3) * 64;      // warp N offset (4 groups of 64)

    const int bm = blockIdx.x * 64;
    const float* const Asrc = x + (size_t)bm * D;

    auto load_stage = [&](int stg, int chunk) {
        const int kc = chunk * 32;
        const uint32_t sb = smem_u + stg * XQ_STAGE;
        // A fp32: 64 rows x 32 floats = 512 cp16
#pragma unroll
        for (int i = 0; i < 2; ++i) {
            const int q = tid + i * 256;
            const int r = q >> 3, ch = q & 7;
            cp16(sb + AF32 + r * 128 + ch * 16,
                 Asrc + (size_t)r * D + kc + ch * 4);
        }
        // B hi / B lo: 256 rows x 4 chunks each
#pragma unroll
        for (int i = 0; i < 4; ++i) {
            const int q = tid + i * 256;
            const int r = q >> 2, ch = q & 3;
            const uint32_t sw = r * 64 + ((ch ^ ((r >> 1) & 3)) << 4);
            cp16(sb + BHI + sw, g_wqt_hi + (size_t)r * D + kc + ch * 8);
            cp16(sb + BLO + sw, g_wqt_lo + (size_t)r * D + kc + ch * 8);
        }
    };

    const int laneA_r = ((lane & 8) ? 8 : 0) + (lane & 7);
    const int laneA_k = (lane & 16) ? 1 : 0;
    const int mi = lane >> 3;
    const int laneB_ns = mi >> 1;
    const int laneB_k  = mi & 1;
    const int laneB_r  = lane & 7;

    float acc[2][2][4][4];   // [mt][half][nt][4]
#pragma unroll
    for (int a = 0; a < 2; ++a)
#pragma unroll
        for (int h = 0; h < 2; ++h)
#pragma unroll
            for (int b = 0; b < 4; ++b)
#pragma unroll
                for (int q = 0; q < 4; ++q) acc[a][h][b][q] = 0.f;

    load_stage(0, 0);
    cp_commit();

#pragma unroll 1
    for (int chunk = 0; chunk < 8; ++chunk) {
        const int stg = chunk & 1;
        if (chunk < 7) {
            load_stage(stg ^ 1, chunk + 1);
            cp_commit();
            cp_wait<1>();
        } else {
            cp_wait<0>();
        }
        __syncthreads();

        const uint32_t sb = smem_u + stg * XQ_STAGE;
        char* const sp = smem + stg * XQ_STAGE;

        // ---- convert A fp32 -> swizzled bf16 hi/lo (8 floats per thread) ----
        {
            const int r = tid >> 2, ch = tid & 3;
            const float4* src = reinterpret_cast<const float4*>(
                sp + AF32 + r * 128 + ch * 32);
            float4 v0 = src[0], v1 = src[1];
            const float vf[8] = { v0.x, v0.y, v0.z, v0.w,
                                  v1.x, v1.y, v1.z, v1.w };
            __nv_bfloat16 hh[8], ll[8];
#pragma unroll
            for (int e = 0; e < 8; ++e) {
                hh[e] = __float2bfloat16_rn(vf[e]);
                ll[e] = __float2bfloat16_rn(vf[e] - __bfloat162float(hh[e]));
            }
            const uint32_t sw = r * 64 + ((ch ^ ((r >> 1) & 3)) << 4);
            *reinterpret_cast<uint4*>(sp + AHI + sw) =
                *reinterpret_cast<const uint4*>(hh);
            *reinterpret_cast<uint4*>(sp + ALO + sw) =
                *reinterpret_cast<const uint4*>(ll);
        }
        __syncthreads();

        // ---- MMA ----
#pragma unroll
        for (int ks = 0; ks < 32; ks += 16) {
            const int ko = (ks >> 3);
            uint32_t aH[2][4], aL[2][4];
#pragma unroll
            for (int mt = 0; mt < 2; ++mt) {
                const int R = wm + mt * 16 + laneA_r;
                const int kk = ko + laneA_k;
                const uint32_t sw = R * 64 + ((kk ^ ((R >> 1) & 3)) << 4);
                LDSM_X4(aH[mt][0], aH[mt][1], aH[mt][2], aH[mt][3],
                        sb + AHI + sw);
                LDSM_X4(aL[mt][0], aL[mt][1], aL[mt][2], aL[mt][3],
                        sb + ALO + sw);
            }
#pragma unroll
            for (int h = 0; h < 2; ++h) {
                uint32_t bH[4][2], bL[4][2];
#pragma unroll
                for (int g = 0; g < 2; ++g) {
                    const int R = wn + h * 32 + (2 * g + laneB_ns) * 8 + laneB_r;
                    const int kk = ko + laneB_k;
                    const uint32_t sw = R * 64 + ((kk ^ ((R >> 1) & 3)) << 4);
                    LDSM_X4(bH[2 * g][0], bH[2 * g][1],
                            bH[2 * g + 1][0], bH[2 * g + 1][1], sb + BHI + sw);
                    LDSM_X4(bL[2 * g][0], bL[2 * g][1],
                            bL[2 * g + 1][0], bL[2 * g + 1][1], sb + BLO + sw);
                }
#pragma unroll
                for (int mt = 0; mt < 2; ++mt)
#pragma unroll
                    for (int nt = 0; nt < 4; ++nt)
                        MMA_BF16(acc[mt][h][nt], aH[mt], bH[nt]);
#pragma unroll
                for (int mt = 0; mt < 2; ++mt)
#pragma unroll
                    for (int nt = 0; nt < 4; ++nt)
                        MMA_BF16(acc[mt][h][nt], aL[mt], bH[nt]);
#pragma unroll
                for (int mt = 0; mt < 2; ++mt)
#pragma unroll
                    for (int nt = 0; nt < 4; ++nt)
                        MMA_BF16(acc[mt][h][nt], aH[mt], bL[nt]);
            }
        }
        __syncthreads();
    }

    // Epilogue with reshape-scramble scale
    const int rbase = bm + wm + (lane >> 2);
    const int cb0 = wn + 2 * (lane & 3);
#pragma unroll
    for (int mt = 0; mt < 2; ++mt) {
        const int R0 = rbase + mt * 16;
        const int R1 = R0 + 8;
        const int t0 = R0 & (T - 1);
        const int t1 = R1 & (T - 1);
#pragma unroll
        for (int h = 0; h < 2; ++h) {
#pragma unroll
            for (int nt = 0; nt < 4; ++nt) {
                const int C = cb0 + h * 32 + nt * 8;
                float2 v01, v23;
                v01.x = acc[mt][h][nt][0] * g_S[(size_t)C * T + t0];
                v01.y = acc[mt][h][nt][1] * g_S[(size_t)(C + 1) * T + t0];
                v23.x = acc[mt][h][nt][2] * g_S[(size_t)C * T + t1];
                v23.y = acc[mt][h][nt][3] * g_S[(size_t)(C + 1) * T + t1];
                *reinterpret_cast<float2*>(&out[(size_t)R0 * D + C]) = v01;
                *reinterpret_cast<float2*>(&out[(size_t)R1 * D + C]) = v23;
            }
        }
    }
}

// ---------------------------------------------------------------------------
extern "C" void kernel_launch(void* const* d_in, const int* in_sizes, int n_in,
                              void* d_out, int out_size) {
    const float* x  = (const float*)d_in[0];
    const float* Wq = (const float*)d_in[1];
    const float* Wk = (const float*)d_in[2];
    const float* Wv = (const float*)d_in[3];
    float* out = (float*)d_out;

    cudaFuncSetAttribute(yk_gemm,
                         cudaFuncAttributeMaxDynamicSharedMemorySize, SMEM_SMALL);
    cudaFuncSetAttribute(xq_gemm,
                         cudaFuncAttributeMaxDynamicSharedMemorySize, SMEM_BIG);

    // A: row-sums of Wv (coalesced)
    wvsum_kernel<<<8, 256>>>(Wv);
    // W: split+transpose Wq/Wk into bf16 hi/lo
    wconv_kernel<<<dim3(2, 8), 256>>>(Wq, Wk);
    // B: vsum fold + y hi/lo
    y_kernel<<<T, 256>>>(x);
    // C: c = y @ Wk via warp-MMA, 64x64 tiles (128 CTAs)
    yk_gemm<<<dim3(T / 64, D / 64), 256, SMEM_SMALL>>>();
    // D: blocked decay scan -> S
    scan_local_kernel<<<SCAN_P, 256>>>();
    scan_carry_kernel<<<1, 256>>>();
    scan_combine_kernel<<<SCAN_P, 256>>>();
    // E: out = S2 .* (x @ Wq), fused x-split, x read once
    xq_gemm<<<MBIG / 64, 256, SMEM_BIG>>>(x, out);
}